// round 1
// baseline (speedup 1.0000x reference)
#include <cuda_runtime.h>
#include <math.h>

#define TT   2048
#define HH   1024
#define NHQ  16
#define NKVH 4
#define HD   64
#define QKVD ((NHQ + 2*NKVH) * HD)   // 1536
#define NE   8
#define NI   2048
#define EPSV 1e-5f

// ---------------- scratch (device globals; no allocations) ----------------
__device__ float g_h      [(size_t)TT * HH];
__device__ float g_qkv    [(size_t)TT * QKVD];
__device__ float g_attn   [(size_t)TT * NHQ * HD];
__device__ float g_resattn[(size_t)TT * HH];
__device__ float g_gu13   [(size_t)TT * 2 * HH];
__device__ float g_silu   [(size_t)TT * HH];
__device__ float g_rmlp   [(size_t)TT * HH];
__device__ float g_m      [(size_t)TT * HH];
__device__ float g_moe    [(size_t)TT * HH];
__device__ int   g_cnt    [NE];
__device__ int   g_tok    [NE * TT];
__device__ float g_wt     [NE * TT];
__device__ float g_xe     [(size_t)NE * TT * HH];
__device__ float g_gu     [(size_t)NE * TT * 2 * NI];
__device__ float g_act    [(size_t)NE * TT * NI];
__device__ float g_eo     [(size_t)NE * TT * HH];

// ---------------- utility kernels ----------------
__global__ void zero_kernel() {
    size_t i = (size_t)blockIdx.x * blockDim.x + threadIdx.x;
    if (i < (size_t)TT * HH) g_moe[i] = 0.0f;
    if (i < NE) g_cnt[i] = 0;
}

__global__ void rmsnorm_kernel(const float* __restrict__ x,
                               const float* __restrict__ w,
                               float* __restrict__ o) {
    int t = blockIdx.x;
    const float* xr = x + (size_t)t * HH;
    __shared__ float red[256];
    float s = 0.0f;
    for (int i = threadIdx.x; i < HH; i += 256) { float v = xr[i]; s += v * v; }
    red[threadIdx.x] = s;
    __syncthreads();
    for (int k = 128; k > 0; k >>= 1) {
        if (threadIdx.x < k) red[threadIdx.x] += red[threadIdx.x + k];
        __syncthreads();
    }
    float rs = rsqrtf(red[0] / (float)HH + EPSV);
    for (int i = threadIdx.x; i < HH; i += 256)
        o[(size_t)t * HH + i] = xr[i] * rs * w[i];
}

__global__ void rope_kernel(float* __restrict__ qkv, const int* __restrict__ positions) {
    int t = blockIdx.x;
    int h = blockIdx.y;               // 0..NHQ+NKVH-1
    int d = threadIdx.x;              // 0..31 (half of HD)
    int off = (h < NHQ) ? h * HD : NHQ * HD + (h - NHQ) * HD;
    float* p = qkv + (size_t)t * QKVD + off;
    float x1 = p[d];
    float x2 = p[d + 32];
    float pos = (float)positions[t];
    float invf = expf(-((float)d / 32.0f) * logf(10000.0f));
    float fr = pos * invf;
    float c = cosf(fr), s = sinf(fr);
    p[d]      = x1 * c - x2 * s;
    p[d + 32] = x2 * c + x1 * s;
}

// ---------------- attention: two-pass softmax per (query, head) ----------------
__global__ void attn_kernel(const float* __restrict__ qkv, float* __restrict__ out) {
    int t = blockIdx.x;
    int h = blockIdx.y;
    int kvh = h >> 2;                 // rep = NHQ / NKVH = 4
    int tid = threadIdx.x;            // 128 threads

    __shared__ float q[HD];
    __shared__ float sc[TT];
    __shared__ float red[128];

    if (tid < HD) q[tid] = qkv[(size_t)t * QKVD + h * HD + tid];
    __syncthreads();

    const float scale = 0.125f;       // 64^-0.5
    float lmax = -1e30f;
    for (int j = tid; j <= t; j += 128) {
        const float* kr = qkv + (size_t)j * QKVD + NHQ * HD + kvh * HD;
        float s = 0.0f;
        #pragma unroll
        for (int d = 0; d < HD; d++) s += q[d] * kr[d];
        s *= scale;
        sc[j] = s;
        lmax = fmaxf(lmax, s);
    }
    red[tid] = lmax; __syncthreads();
    for (int k = 64; k > 0; k >>= 1) {
        if (tid < k) red[tid] = fmaxf(red[tid], red[tid + k]);
        __syncthreads();
    }
    float mx = red[0];
    __syncthreads();

    float lsum = 0.0f;
    for (int j = tid; j <= t; j += 128) {
        float p = expf(sc[j] - mx);
        sc[j] = p;
        lsum += p;
    }
    red[tid] = lsum; __syncthreads();
    for (int k = 64; k > 0; k >>= 1) {
        if (tid < k) red[tid] += red[tid + k];
        __syncthreads();
    }
    float inv = 1.0f / red[0];
    __syncthreads();

    // output: 2 partitions of 64 threads split the j loop
    int d = tid & 63;
    int part = tid >> 6;
    const float* vbase = qkv + NHQ * HD + NKVH * HD + kvh * HD + d;
    float acc = 0.0f;
    #pragma unroll 4
    for (int j = part; j <= t; j += 2)
        acc += sc[j] * vbase[(size_t)j * QKVD];
    red[tid] = acc;
    __syncthreads();
    if (tid < 64)
        out[(size_t)t * (NHQ * HD) + h * HD + tid] = (red[tid] + red[tid + 64]) * inv;
}

// ---------------- tiled SGEMM: C = A(MxK) * B(NxK)^T (+ optional addend) ----------------
__device__ __forceinline__ void sgemm_body(const float* __restrict__ A,
                                           const float* __restrict__ B,
                                           float* __restrict__ C,
                                           const float* __restrict__ Dadd,
                                           int M, int N, int K) {
    __shared__ float As[64][17];
    __shared__ float Bs[64][17];
    int tid = threadIdx.x;
    int tx = tid & 15, ty = tid >> 4;
    int row0 = blockIdx.y * 64, col0 = blockIdx.x * 64;
    float acc[4][4] = {};

    int lr = tid >> 2;
    int lc = (tid & 3) * 4;
    for (int k0 = 0; k0 < K; k0 += 16) {
        // load A tile (rows may exceed M for grouped case; reads stay in-buffer)
        {
            const float* ap = A + (size_t)(row0 + lr) * K + k0 + lc;
            As[lr][lc + 0] = ap[0]; As[lr][lc + 1] = ap[1];
            As[lr][lc + 2] = ap[2]; As[lr][lc + 3] = ap[3];
        }
        {
            const float* bp = B + (size_t)(col0 + lr) * K + k0 + lc;
            Bs[lr][lc + 0] = bp[0]; Bs[lr][lc + 1] = bp[1];
            Bs[lr][lc + 2] = bp[2]; Bs[lr][lc + 3] = bp[3];
        }
        __syncthreads();
        #pragma unroll
        for (int kk = 0; kk < 16; kk++) {
            float a[4], b[4];
            #pragma unroll
            for (int i = 0; i < 4; i++) a[i] = As[ty * 4 + i][kk];
            #pragma unroll
            for (int j = 0; j < 4; j++) b[j] = Bs[tx * 4 + j][kk];
            #pragma unroll
            for (int i = 0; i < 4; i++)
                #pragma unroll
                for (int j = 0; j < 4; j++)
                    acc[i][j] += a[i] * b[j];
        }
        __syncthreads();
    }
    #pragma unroll
    for (int i = 0; i < 4; i++) {
        int rr = row0 + ty * 4 + i;
        if (rr >= M) continue;
        #pragma unroll
        for (int j = 0; j < 4; j++) {
            int cc = col0 + tx * 4 + j;
            float v = acc[i][j];
            if (Dadd) v += Dadd[(size_t)rr * N + cc];
            C[(size_t)rr * N + cc] = v;
        }
    }
}

__global__ void sgemm_nt_kernel(const float* A, const float* B, float* C,
                                const float* Dadd, int M, int N, int K) {
    sgemm_body(A, B, C, Dadd, M, N, K);
}

__global__ void sgemm_grouped_kernel(const float* A, const float* B, float* C,
                                     int N, int K,
                                     long long Asl, long long Bsl, long long Csl) {
    int e = blockIdx.z;
    int M = g_cnt[e];
    if ((int)blockIdx.y * 64 >= M) return;
    sgemm_body(A + (size_t)e * Asl, B + (size_t)e * Bsl, C + (size_t)e * Csl,
               nullptr, M, N, K);
}

// ---------------- silu_and_mul ----------------
__global__ void silu_kernel(const float* __restrict__ gu, float* __restrict__ o, int width) {
    int t = blockIdx.x;
    const float* g = gu + (size_t)t * 2 * width;
    const float* u = g + width;
    for (int i = threadIdx.x; i < width; i += 256) {
        float gv = g[i];
        float s = gv / (1.0f + expf(-gv));
        o[(size_t)t * width + i] = s * u[i];
    }
}

__global__ void silu_grouped_kernel() {
    int e = blockIdx.y, r = blockIdx.x;
    if (r >= g_cnt[e]) return;
    const float* g = g_gu + ((size_t)e * TT + r) * (2 * NI);
    const float* u = g + NI;
    float* o = g_act + ((size_t)e * TT + r) * NI;
    for (int i = threadIdx.x; i < NI; i += 256) {
        float gv = g[i];
        float s = gv / (1.0f + expf(-gv));
        o[i] = s * u[i];
    }
}

// ---------------- MoE routing ----------------
__global__ void gate_kernel(const float* __restrict__ m, const float* __restrict__ gw) {
    int t = blockIdx.x;
    __shared__ float logits[NE];
    int warp = threadIdx.x >> 5, lane = threadIdx.x & 31;   // 8 warps = 8 experts
    const float* xr = m + (size_t)t * HH;
    const float* wr = gw + (size_t)warp * HH;
    float s = 0.0f;
    for (int i = lane; i < HH; i += 32) s += xr[i] * wr[i];
    for (int o = 16; o > 0; o >>= 1) s += __shfl_down_sync(0xffffffffu, s, o);
    if (lane == 0) logits[warp] = s;
    __syncthreads();
    if (threadIdx.x == 0) {
        float mx = logits[0];
        for (int e = 1; e < NE; e++) mx = fmaxf(mx, logits[e]);
        float p[NE]; float sum = 0.0f;
        for (int e = 0; e < NE; e++) { p[e] = expf(logits[e] - mx); sum += p[e]; }
        for (int e = 0; e < NE; e++) p[e] /= sum;
        int i0 = 0;
        for (int e = 1; e < NE; e++) if (p[e] > p[i0]) i0 = e;
        int i1 = (i0 == 0) ? 1 : 0;
        for (int e = 0; e < NE; e++) if (e != i0 && p[e] > p[i1]) i1 = e;
        float inv = 1.0f / (p[i0] + p[i1]);
        int pos0 = atomicAdd(&g_cnt[i0], 1);
        g_tok[i0 * TT + pos0] = t; g_wt[i0 * TT + pos0] = p[i0] * inv;
        int pos1 = atomicAdd(&g_cnt[i1], 1);
        g_tok[i1 * TT + pos1] = t; g_wt[i1 * TT + pos1] = p[i1] * inv;
    }
}

__global__ void gather_kernel(const float* __restrict__ m) {
    int e = blockIdx.y, r = blockIdx.x;
    if (r >= g_cnt[e]) return;
    int t = g_tok[e * TT + r];
    const float* src = m + (size_t)t * HH;
    float* dst = g_xe + ((size_t)e * TT + r) * HH;
    for (int i = threadIdx.x; i < HH; i += 256) dst[i] = src[i];
}

__global__ void scatter_kernel() {
    int e = blockIdx.y, r = blockIdx.x;
    if (r >= g_cnt[e]) return;
    int t = g_tok[e * TT + r];
    float w = g_wt[e * TT + r];
    const float* src = g_eo + ((size_t)e * TT + r) * HH;
    float* dst = g_moe + (size_t)t * HH;
    for (int i = threadIdx.x; i < HH; i += 256) atomicAdd(&dst[i], w * src[i]);
}

__global__ void final_kernel(const float* __restrict__ rmlp, float* __restrict__ out) {
    size_t i = (size_t)blockIdx.x * blockDim.x + threadIdx.x;
    if (i < (size_t)TT * HH) out[i] = rmlp[i] + g_moe[i];
}

// ---------------- launch ----------------
extern "C" void kernel_launch(void* const* d_in, const int* in_sizes, int n_in,
                              void* d_out, int out_size) {
    (void)in_sizes; (void)n_in; (void)out_size;
    const int*   positions = (const int*)  d_in[0];
    const float* hidden    = (const float*)d_in[1];
    const float* input_ln  = (const float*)d_in[2];
    const float* post_ln   = (const float*)d_in[3];
    const float* resid_ln  = (const float*)d_in[4];
    const float* qkv_w     = (const float*)d_in[5];
    const float* o_w       = (const float*)d_in[6];
    const float* gate_w    = (const float*)d_in[7];
    const float* ws        = (const float*)d_in[8];
    const float* w2s       = (const float*)d_in[9];
    const float* w13       = (const float*)d_in[10];
    const float* w2        = (const float*)d_in[11];
    float* out = (float*)d_out;

    float *p_h, *p_qkv, *p_attn, *p_resattn, *p_gu13, *p_silu, *p_rmlp, *p_m;
    float *p_xe, *p_gu, *p_act, *p_eo;
    cudaGetSymbolAddress((void**)&p_h,       g_h);
    cudaGetSymbolAddress((void**)&p_qkv,     g_qkv);
    cudaGetSymbolAddress((void**)&p_attn,    g_attn);
    cudaGetSymbolAddress((void**)&p_resattn, g_resattn);
    cudaGetSymbolAddress((void**)&p_gu13,    g_gu13);
    cudaGetSymbolAddress((void**)&p_silu,    g_silu);
    cudaGetSymbolAddress((void**)&p_rmlp,    g_rmlp);
    cudaGetSymbolAddress((void**)&p_m,       g_m);
    cudaGetSymbolAddress((void**)&p_xe,      g_xe);
    cudaGetSymbolAddress((void**)&p_gu,      g_gu);
    cudaGetSymbolAddress((void**)&p_act,     g_act);
    cudaGetSymbolAddress((void**)&p_eo,      g_eo);

    zero_kernel<<<(TT * HH + 255) / 256, 256>>>();

    // h = rms_norm(hidden, input_ln_w)
    rmsnorm_kernel<<<TT, 256>>>(hidden, input_ln, p_h);

    // qkv = h @ qkv_w.T
    sgemm_nt_kernel<<<dim3(QKVD / 64, TT / 64), 256>>>(p_h, qkv_w, p_qkv, nullptr, TT, QKVD, HH);

    // rope on q,k
    rope_kernel<<<dim3(TT, NHQ + NKVH), 32>>>(p_qkv, positions);

    // attention
    attn_kernel<<<dim3(TT, NHQ), 128>>>(p_qkv, p_attn);

    // residual_attn = hidden + attn @ o_w.T
    sgemm_nt_kernel<<<dim3(HH / 64, TT / 64), 256>>>(p_attn, o_w, p_resattn, hidden, TT, HH, NHQ * HD);

    // residual MLP: r = rms_norm(resattn) ; gu13 = r @ w13.T ; silu ; rmlp = resattn + silu @ w2.T
    rmsnorm_kernel<<<TT, 256>>>(p_resattn, resid_ln, p_h);
    sgemm_nt_kernel<<<dim3(2 * HH / 64, TT / 64), 256>>>(p_h, w13, p_gu13, nullptr, TT, 2 * HH, HH);
    silu_kernel<<<TT, 256>>>(p_gu13, p_silu, HH);
    sgemm_nt_kernel<<<dim3(HH / 64, TT / 64), 256>>>(p_silu, w2, p_rmlp, p_resattn, TT, HH, HH);

    // MoE on m = rms_norm(resattn, post_ln)
    rmsnorm_kernel<<<TT, 256>>>(p_resattn, post_ln, p_m);
    gate_kernel<<<TT, 256>>>(p_m, gate_w);
    gather_kernel<<<dim3(TT, NE), 256>>>(p_m);
    sgemm_grouped_kernel<<<dim3(2 * NI / 64, TT / 64, NE), 256>>>(
        p_xe, ws, p_gu, 2 * NI, HH,
        (long long)TT * HH, (long long)2 * NI * HH, (long long)TT * 2 * NI);
    silu_grouped_kernel<<<dim3(TT, NE), 256>>>();
    sgemm_grouped_kernel<<<dim3(HH / 64, TT / 64, NE), 256>>>(
        p_act, w2s, p_eo, HH, NI,
        (long long)TT * NI, (long long)HH * NI, (long long)TT * HH);
    scatter_kernel<<<dim3(TT, NE), 256>>>();

    // out = (resattn + r) + moe
    final_kernel<<<(TT * HH + 255) / 256, 256>>>(p_rmlp, out);
}

// round 2
// speedup vs baseline: 4.3674x; 4.3674x over previous
#include <cuda_runtime.h>
#include <math.h>

#define TT   2048
#define HH   1024
#define NHQ  16
#define NKVH 4
#define HD   64
#define QKVD ((NHQ + 2*NKVH) * HD)   // 1536
#define NE   8
#define NI   2048
#define EPSV 1e-5f

// ---------------- scratch (device globals; no allocations) ----------------
__device__ float g_h      [(size_t)TT * HH];
__device__ float g_qkv    [(size_t)TT * QKVD];
__device__ float g_attn   [(size_t)TT * NHQ * HD];
__device__ float g_resattn[(size_t)TT * HH];
__device__ float g_gu13   [(size_t)TT * 2 * HH];
__device__ float g_silu   [(size_t)TT * HH];
__device__ float g_rmlp   [(size_t)TT * HH];
__device__ float g_m      [(size_t)TT * HH];
__device__ int   g_cnt    [NE];
__device__ int   g_tok    [NE * TT];
__device__ float g_wt     [NE * TT];
__device__ float g_xe     [(size_t)NE * TT * HH];
__device__ float g_gu     [(size_t)NE * TT * 2 * NI];
__device__ float g_act    [(size_t)NE * TT * NI];
__device__ float g_eo     [(size_t)NE * TT * HH];

// ---------------- utility kernels ----------------
__global__ void zero_cnt_kernel() {
    if (threadIdx.x < NE) g_cnt[threadIdx.x] = 0;
}

__global__ void rmsnorm_kernel(const float* __restrict__ x,
                               const float* __restrict__ w,
                               float* __restrict__ o) {
    int t = blockIdx.x;
    const float4* xr = (const float4*)(x + (size_t)t * HH);
    const float4* wr = (const float4*)w;
    float4 xv = xr[threadIdx.x];
    float s = xv.x * xv.x + xv.y * xv.y + xv.z * xv.z + xv.w * xv.w;
    __shared__ float red[256];
    red[threadIdx.x] = s;
    __syncthreads();
    for (int k = 128; k > 0; k >>= 1) {
        if (threadIdx.x < k) red[threadIdx.x] += red[threadIdx.x + k];
        __syncthreads();
    }
    float rs = rsqrtf(red[0] / (float)HH + EPSV);
    float4 wv = wr[threadIdx.x];
    float4 ov = make_float4(xv.x * rs * wv.x, xv.y * rs * wv.y,
                            xv.z * rs * wv.z, xv.w * rs * wv.w);
    ((float4*)(o + (size_t)t * HH))[threadIdx.x] = ov;
}

__global__ void rope_kernel(float* __restrict__ qkv, const int* __restrict__ positions) {
    int t = blockIdx.x;
    int h = blockIdx.y;               // 0..NHQ+NKVH-1
    int d = threadIdx.x;              // 0..31 (half of HD)
    int off = (h < NHQ) ? h * HD : NHQ * HD + (h - NHQ) * HD;
    float* p = qkv + (size_t)t * QKVD + off;
    float x1 = p[d];
    float x2 = p[d + 32];
    float pos = (float)positions[t];
    float invf = __expf(-((float)d / 32.0f) * logf(10000.0f));
    float fr = pos * invf;
    float c, s;
    __sincosf(fr, &s, &c);
    p[d]      = x1 * c - x2 * s;
    p[d + 32] = x2 * c + x1 * s;
}

// ---------------- flash attention: 64-query x 32-key tiles ----------------
#define BR 64
#define BC 32
__global__ __launch_bounds__(256) void attn_flash_kernel(
    const float* __restrict__ qkv, float* __restrict__ out) {
    int qt = blockIdx.x, h = blockIdx.y;
    int kvh = h >> 2;                  // rep = 4
    int tid = threadIdx.x;
    int tx = tid & 15, ty = tid >> 4;

    __shared__ float Qs[BR][HD + 1];
    __shared__ float Ks[BC][HD + 1];
    __shared__ float Vs[BC][HD];
    __shared__ float Ps[BR][BC + 1];
    __shared__ float sm[BR], sl[BR], scor[BR];

    // load Q tile (64 rows x 64 cols)
    for (int i = tid; i < BR * 16; i += 256) {
        int r = i >> 4, c = (i & 15) << 2;
        float4 v = *(const float4*)&qkv[(size_t)(qt * BR + r) * QKVD + h * HD + c];
        Qs[r][c] = v.x; Qs[r][c + 1] = v.y; Qs[r][c + 2] = v.z; Qs[r][c + 3] = v.w;
    }
    if (tid < BR) { sm[tid] = -1e30f; sl[tid] = 0.0f; }

    float acc[4][4] = {};
    int ktmax = (qt * BR + BR - 1) / BC;
    for (int kt = 0; kt <= ktmax; kt++) {
        __syncthreads();               // guards Q/stat init and K/V/P reuse
        for (int i = tid; i < BC * 16; i += 256) {
            int r = i >> 4, c = (i & 15) << 2;
            size_t base = (size_t)(kt * BC + r) * QKVD + NHQ * HD + kvh * HD;
            float4 kv = *(const float4*)&qkv[base + c];
            Ks[r][c] = kv.x; Ks[r][c + 1] = kv.y; Ks[r][c + 2] = kv.z; Ks[r][c + 3] = kv.w;
            float4 vv = *(const float4*)&qkv[base + NKVH * HD + c];
            *(float4*)&Vs[r][c] = vv;
        }
        __syncthreads();

        // GEMM1: S = Q @ K^T  (each thread: 4 q-rows x 2 k-cols)
        float s[4][2] = {};
        #pragma unroll 8
        for (int d = 0; d < HD; d++) {
            float b0 = Ks[tx * 2][d], b1 = Ks[tx * 2 + 1][d];
            #pragma unroll
            for (int i = 0; i < 4; i++) {
                float a = Qs[ty * 4 + i][d];
                s[i][0] += a * b0;
                s[i][1] += a * b1;
            }
        }
        #pragma unroll
        for (int i = 0; i < 4; i++)
            #pragma unroll
            for (int j = 0; j < 2; j++) {
                int qg = qt * BR + ty * 4 + i;
                int kg = kt * BC + tx * 2 + j;
                Ps[ty * 4 + i][tx * 2 + j] = (kg <= qg) ? s[i][j] * 0.125f : -1e30f;
            }
        __syncthreads();

        // row-wise online softmax (64 threads, one per row)
        if (tid < BR) {
            int r = tid;
            float rm = -1e30f;
            #pragma unroll 8
            for (int j = 0; j < BC; j++) rm = fmaxf(rm, Ps[r][j]);
            float newm = fmaxf(sm[r], rm);
            float corr = __expf(sm[r] - newm);
            float sum = 0.0f;
            #pragma unroll 8
            for (int j = 0; j < BC; j++) {
                float p = __expf(Ps[r][j] - newm);
                Ps[r][j] = p;
                sum += p;
            }
            sl[r] = sl[r] * corr + sum;
            sm[r] = newm;
            scor[r] = corr;
        }
        __syncthreads();

        // O = O*corr + P @ V  (each thread: 4 q-rows x 4 d-cols)
        float c0[4];
        #pragma unroll
        for (int i = 0; i < 4; i++) c0[i] = scor[ty * 4 + i];
        #pragma unroll
        for (int i = 0; i < 4; i++)
            #pragma unroll
            for (int j = 0; j < 4; j++) acc[i][j] *= c0[i];
        #pragma unroll 4
        for (int jj = 0; jj < BC; jj++) {
            float4 b = *(const float4*)&Vs[jj][tx * 4];
            #pragma unroll
            for (int i = 0; i < 4; i++) {
                float a = Ps[ty * 4 + i][jj];
                acc[i][0] += a * b.x; acc[i][1] += a * b.y;
                acc[i][2] += a * b.z; acc[i][3] += a * b.w;
            }
        }
    }

    #pragma unroll
    for (int i = 0; i < 4; i++) {
        int qg = qt * BR + ty * 4 + i;
        float inv = 1.0f / sl[ty * 4 + i];
        float4 v = make_float4(acc[i][0] * inv, acc[i][1] * inv,
                               acc[i][2] * inv, acc[i][3] * inv);
        *(float4*)&out[(size_t)qg * (NHQ * HD) + h * HD + tx * 4] = v;
    }
}

// ---------------- 128x128x8 double-buffered SGEMM: C = A * B^T (+Dadd) ----------------
__device__ __forceinline__ void sgemm128_body(
    const float* __restrict__ A, const float* __restrict__ B,
    float* __restrict__ C, const float* __restrict__ Dadd,
    int M, int N, int K) {
    __shared__ float As[2][8][128];
    __shared__ float Bs[2][8][128];
    const int tid = threadIdx.x;
    const int lr = tid >> 1;
    const int lc = (tid & 1) << 2;
    const int tx = tid & 15;
    const int ty = tid >> 4;
    const int row0 = blockIdx.y * 128;
    const int col0 = blockIdx.x * 128;

    int arow = row0 + lr; if (arow >= M) arow = M - 1;   // clamp (grouped ragged M)
    const float* aptr = A + (size_t)arow * K + lc;
    const float* bptr = B + (size_t)(col0 + lr) * K + lc;

    float acc[8][8] = {};
    float4 av = *(const float4*)aptr;
    float4 bv = *(const float4*)bptr;
    As[0][lc + 0][lr] = av.x; As[0][lc + 1][lr] = av.y;
    As[0][lc + 2][lr] = av.z; As[0][lc + 3][lr] = av.w;
    Bs[0][lc + 0][lr] = bv.x; Bs[0][lc + 1][lr] = bv.y;
    Bs[0][lc + 2][lr] = bv.z; Bs[0][lc + 3][lr] = bv.w;
    __syncthreads();

    const int nt = K >> 3;
    for (int kt = 0; kt < nt; kt++) {
        int cur = kt & 1;
        if (kt + 1 < nt) {
            av = *(const float4*)(aptr + (kt + 1) * 8);
            bv = *(const float4*)(bptr + (kt + 1) * 8);
        }
        #pragma unroll
        for (int kk = 0; kk < 8; kk++) {
            float4 a0 = *(const float4*)&As[cur][kk][ty * 8];
            float4 a1 = *(const float4*)&As[cur][kk][ty * 8 + 4];
            float4 b0 = *(const float4*)&Bs[cur][kk][tx * 8];
            float4 b1 = *(const float4*)&Bs[cur][kk][tx * 8 + 4];
            float a[8] = {a0.x, a0.y, a0.z, a0.w, a1.x, a1.y, a1.z, a1.w};
            float b[8] = {b0.x, b0.y, b0.z, b0.w, b1.x, b1.y, b1.z, b1.w};
            #pragma unroll
            for (int i = 0; i < 8; i++)
                #pragma unroll
                for (int j = 0; j < 8; j++)
                    acc[i][j] += a[i] * b[j];
        }
        if (kt + 1 < nt) {
            int nb = cur ^ 1;
            As[nb][lc + 0][lr] = av.x; As[nb][lc + 1][lr] = av.y;
            As[nb][lc + 2][lr] = av.z; As[nb][lc + 3][lr] = av.w;
            Bs[nb][lc + 0][lr] = bv.x; Bs[nb][lc + 1][lr] = bv.y;
            Bs[nb][lc + 2][lr] = bv.z; Bs[nb][lc + 3][lr] = bv.w;
        }
        __syncthreads();
    }

    #pragma unroll
    for (int i = 0; i < 8; i++) {
        int rr = row0 + ty * 8 + i;
        if (rr >= M) continue;
        #pragma unroll
        for (int jj = 0; jj < 8; jj += 4) {
            int cc = col0 + tx * 8 + jj;
            float4 v = make_float4(acc[i][jj], acc[i][jj + 1], acc[i][jj + 2], acc[i][jj + 3]);
            if (Dadd) {
                float4 d = *(const float4*)&Dadd[(size_t)rr * N + cc];
                v.x += d.x; v.y += d.y; v.z += d.z; v.w += d.w;
            }
            *(float4*)&C[(size_t)rr * N + cc] = v;
        }
    }
}

__global__ __launch_bounds__(256) void sgemm_nt_kernel(
    const float* A, const float* B, float* C, const float* Dadd, int M, int N, int K) {
    sgemm128_body(A, B, C, Dadd, M, N, K);
}

__global__ __launch_bounds__(256) void sgemm_grouped_kernel(
    const float* A, const float* B, float* C, int N, int K,
    long long Asl, long long Bsl, long long Csl) {
    int e = blockIdx.z;
    int M = g_cnt[e];
    if ((int)blockIdx.y * 128 >= M) return;
    sgemm128_body(A + (size_t)e * Asl, B + (size_t)e * Bsl, C + (size_t)e * Csl,
                  nullptr, M, N, K);
}

// ---------------- silu_and_mul ----------------
__global__ void silu_kernel(const float* __restrict__ gu, float* __restrict__ o, int width) {
    int t = blockIdx.x;
    const float4* g = (const float4*)(gu + (size_t)t * 2 * width);
    const float4* u = (const float4*)(gu + (size_t)t * 2 * width + width);
    float4* op = (float4*)(o + (size_t)t * width);
    int w4 = width >> 2;
    for (int i = threadIdx.x; i < w4; i += 256) {
        float4 gv = g[i], uv = u[i];
        float4 r;
        r.x = gv.x / (1.0f + __expf(-gv.x)) * uv.x;
        r.y = gv.y / (1.0f + __expf(-gv.y)) * uv.y;
        r.z = gv.z / (1.0f + __expf(-gv.z)) * uv.z;
        r.w = gv.w / (1.0f + __expf(-gv.w)) * uv.w;
        op[i] = r;
    }
}

__global__ void silu_grouped_kernel() {
    int e = blockIdx.y, r = blockIdx.x;
    if (r >= g_cnt[e]) return;
    const float4* g = (const float4*)(g_gu + ((size_t)e * TT + r) * (2 * NI));
    const float4* u = (const float4*)(g_gu + ((size_t)e * TT + r) * (2 * NI) + NI);
    float4* o = (float4*)(g_act + ((size_t)e * TT + r) * NI);
    for (int i = threadIdx.x; i < NI / 4; i += 256) {
        float4 gv = g[i], uv = u[i];
        float4 rr;
        rr.x = gv.x / (1.0f + __expf(-gv.x)) * uv.x;
        rr.y = gv.y / (1.0f + __expf(-gv.y)) * uv.y;
        rr.z = gv.z / (1.0f + __expf(-gv.z)) * uv.z;
        rr.w = gv.w / (1.0f + __expf(-gv.w)) * uv.w;
        o[i] = rr;
    }
}

// ---------------- MoE routing ----------------
__global__ void gate_kernel(const float* __restrict__ m, const float* __restrict__ gw) {
    int t = blockIdx.x;
    __shared__ float logits[NE];
    int warp = threadIdx.x >> 5, lane = threadIdx.x & 31;   // 8 warps = 8 experts
    const float* xr = m + (size_t)t * HH;
    const float* wr = gw + (size_t)warp * HH;
    float s = 0.0f;
    for (int i = lane; i < HH; i += 32) s += xr[i] * wr[i];
    for (int o = 16; o > 0; o >>= 1) s += __shfl_down_sync(0xffffffffu, s, o);
    if (lane == 0) logits[warp] = s;
    __syncthreads();
    if (threadIdx.x == 0) {
        float mx = logits[0];
        for (int e = 1; e < NE; e++) mx = fmaxf(mx, logits[e]);
        float p[NE]; float sum = 0.0f;
        for (int e = 0; e < NE; e++) { p[e] = __expf(logits[e] - mx); sum += p[e]; }
        for (int e = 0; e < NE; e++) p[e] /= sum;
        int i0 = 0;
        for (int e = 1; e < NE; e++) if (p[e] > p[i0]) i0 = e;
        int i1 = (i0 == 0) ? 1 : 0;
        for (int e = 0; e < NE; e++) if (e != i0 && p[e] > p[i1]) i1 = e;
        float inv = 1.0f / (p[i0] + p[i1]);
        int pos0 = atomicAdd(&g_cnt[i0], 1);
        g_tok[i0 * TT + pos0] = t; g_wt[i0 * TT + pos0] = p[i0] * inv;
        int pos1 = atomicAdd(&g_cnt[i1], 1);
        g_tok[i1 * TT + pos1] = t; g_wt[i1 * TT + pos1] = p[i1] * inv;
    }
}

__global__ void gather_kernel(const float* __restrict__ m) {
    int e = blockIdx.y, r = blockIdx.x;
    if (r >= g_cnt[e]) return;
    int t = g_tok[e * TT + r];
    const float4* src = (const float4*)(m + (size_t)t * HH);
    float4* dst = (float4*)(g_xe + ((size_t)e * TT + r) * HH);
    if (threadIdx.x < HH / 4) dst[threadIdx.x] = src[threadIdx.x];
}

__global__ void scatter_kernel(float* __restrict__ out) {
    int e = blockIdx.y, r = blockIdx.x;
    if (r >= g_cnt[e]) return;
    int t = g_tok[e * TT + r];
    float w = g_wt[e * TT + r];
    const float* src = g_eo + ((size_t)e * TT + r) * HH;
    float* dst = out + (size_t)t * HH;
    for (int i = threadIdx.x; i < HH; i += 256) atomicAdd(&dst[i], w * src[i]);
}

// ---------------- launch ----------------
extern "C" void kernel_launch(void* const* d_in, const int* in_sizes, int n_in,
                              void* d_out, int out_size) {
    (void)in_sizes; (void)n_in; (void)out_size;
    const int*   positions = (const int*)  d_in[0];
    const float* hidden    = (const float*)d_in[1];
    const float* input_ln  = (const float*)d_in[2];
    const float* post_ln   = (const float*)d_in[3];
    const float* resid_ln  = (const float*)d_in[4];
    const float* qkv_w     = (const float*)d_in[5];
    const float* o_w       = (const float*)d_in[6];
    const float* gate_w    = (const float*)d_in[7];
    const float* ws        = (const float*)d_in[8];
    const float* w2s       = (const float*)d_in[9];
    const float* w13       = (const float*)d_in[10];
    const float* w2        = (const float*)d_in[11];
    float* out = (float*)d_out;

    float *p_h, *p_qkv, *p_attn, *p_resattn, *p_gu13, *p_silu, *p_rmlp, *p_m;
    float *p_xe, *p_gu, *p_act, *p_eo;
    cudaGetSymbolAddress((void**)&p_h,       g_h);
    cudaGetSymbolAddress((void**)&p_qkv,     g_qkv);
    cudaGetSymbolAddress((void**)&p_attn,    g_attn);
    cudaGetSymbolAddress((void**)&p_resattn, g_resattn);
    cudaGetSymbolAddress((void**)&p_gu13,    g_gu13);
    cudaGetSymbolAddress((void**)&p_silu,    g_silu);
    cudaGetSymbolAddress((void**)&p_rmlp,    g_rmlp);
    cudaGetSymbolAddress((void**)&p_m,       g_m);
    cudaGetSymbolAddress((void**)&p_xe,      g_xe);
    cudaGetSymbolAddress((void**)&p_gu,      g_gu);
    cudaGetSymbolAddress((void**)&p_act,     g_act);
    cudaGetSymbolAddress((void**)&p_eo,      g_eo);

    zero_cnt_kernel<<<1, 32>>>();

    // h = rms_norm(hidden, input_ln_w)
    rmsnorm_kernel<<<TT, 256>>>(hidden, input_ln, p_h);

    // qkv = h @ qkv_w.T
    sgemm_nt_kernel<<<dim3(QKVD / 128, TT / 128), 256>>>(p_h, qkv_w, p_qkv, nullptr, TT, QKVD, HH);

    // rope on q,k
    rope_kernel<<<dim3(TT, NHQ + NKVH), 32>>>(p_qkv, positions);

    // attention (flash-style)
    attn_flash_kernel<<<dim3(TT / BR, NHQ), 256>>>(p_qkv, p_attn);

    // residual_attn = hidden + attn @ o_w.T
    sgemm_nt_kernel<<<dim3(HH / 128, TT / 128), 256>>>(p_attn, o_w, p_resattn, hidden, TT, HH, NHQ * HD);

    // residual MLP
    rmsnorm_kernel<<<TT, 256>>>(p_resattn, resid_ln, p_h);
    sgemm_nt_kernel<<<dim3(2 * HH / 128, TT / 128), 256>>>(p_h, w13, p_gu13, nullptr, TT, 2 * HH, HH);
    silu_kernel<<<TT, 256>>>(p_gu13, p_silu, HH);
    sgemm_nt_kernel<<<dim3(HH / 128, TT / 128), 256>>>(p_silu, w2, p_rmlp, p_resattn, TT, HH, HH);

    // out starts as residual_mlp; MoE scatters into it
    cudaMemcpyAsync(out, p_rmlp, (size_t)TT * HH * sizeof(float), cudaMemcpyDeviceToDevice);

    // MoE on m = rms_norm(resattn, post_ln)
    rmsnorm_kernel<<<TT, 256>>>(p_resattn, post_ln, p_m);
    gate_kernel<<<TT, 256>>>(p_m, gate_w);
    gather_kernel<<<dim3(TT, NE), 256>>>(p_m);
    sgemm_grouped_kernel<<<dim3(2 * NI / 128, TT / 128, NE), 256>>>(
        p_xe, ws, p_gu, 2 * NI, HH,
        (long long)TT * HH, (long long)2 * NI * HH, (long long)TT * 2 * NI);
    silu_grouped_kernel<<<dim3(TT, NE), 256>>>();
    sgemm_grouped_kernel<<<dim3(HH / 128, TT / 128, NE), 256>>>(
        p_act, w2s, p_eo, HH, NI,
        (long long)TT * NI, (long long)HH * NI, (long long)TT * HH);
    scatter_kernel<<<dim3(TT, NE), 256>>>(out);
}

// round 3
// speedup vs baseline: 7.1926x; 1.6469x over previous
#include <cuda_runtime.h>
#include <cuda_bf16.h>
#include <math.h>
#include <stdint.h>

#define TT   2048
#define HH   1024
#define NHQ  16
#define NKVH 4
#define HD   64
#define QKVD ((NHQ + 2*NKVH) * HD)   // 1536
#define NE   8
#define NI   2048
#define EPSV 1e-5f

typedef __nv_bfloat16 bf16;

// ---------------- scratch (device globals; no allocations) ----------------
__device__ float g_qkv    [(size_t)TT * QKVD];
__device__ float g_resattn[(size_t)TT * HH];
__device__ float g_gu13   [(size_t)TT * 2 * HH];
__device__ float g_rmlp   [(size_t)TT * HH];
__device__ float g_m      [(size_t)TT * HH];
__device__ int   g_cnt    [NE];
__device__ int   g_tok    [NE * TT];
__device__ float g_wt     [NE * TT];
__device__ float g_gu     [(size_t)NE * TT * 2 * NI];
__device__ float g_eo     [(size_t)NE * TT * HH];

// bf16 split buffers: row-major M x 2K with [hi | lo] along K
__device__ __align__(16) bf16 s_h   [(size_t)TT * 2 * HH];
__device__ __align__(16) bf16 s_attn[(size_t)TT * 2 * HH];
__device__ __align__(16) bf16 s_silu[(size_t)TT * 2 * HH];
__device__ __align__(16) bf16 s_qkvw[(size_t)QKVD * 2 * HH];
__device__ __align__(16) bf16 s_ow  [(size_t)HH * 2 * HH];
__device__ __align__(16) bf16 s_w13 [(size_t)2 * HH * 2 * HH];
__device__ __align__(16) bf16 s_w2  [(size_t)HH * 2 * HH];
__device__ __align__(16) bf16 s_ws  [(size_t)NE * 2 * NI * 2 * HH];
__device__ __align__(16) bf16 s_w2s [(size_t)NE * HH * 2 * NI];
__device__ __align__(16) bf16 s_xe  [(size_t)NE * TT * 2 * HH];
__device__ __align__(16) bf16 s_act [(size_t)NE * TT * 2 * NI];

// ---------------- helpers ----------------
__device__ __forceinline__ void split2(float x, bf16& hi, bf16& lo) {
    hi = __float2bfloat16(x);
    lo = __float2bfloat16(x - __bfloat162float(hi));
}

__device__ __forceinline__ void mma16816(float* c, const uint32_t* a, const uint32_t* b) {
    asm volatile(
        "mma.sync.aligned.m16n8k16.row.col.f32.bf16.bf16.f32 "
        "{%0,%1,%2,%3}, {%4,%5,%6,%7}, {%8,%9}, {%0,%1,%2,%3};"
        : "+f"(c[0]), "+f"(c[1]), "+f"(c[2]), "+f"(c[3])
        : "r"(a[0]), "r"(a[1]), "r"(a[2]), "r"(a[3]), "r"(b[0]), "r"(b[1]));
}

// ---------------- utility kernels ----------------
__global__ void zero_cnt_kernel() {
    if (threadIdx.x < NE) g_cnt[threadIdx.x] = 0;
}

// generic fp32 -> bf16 split (rows x K -> rows x 2K)
__global__ void split_kernel(const float* __restrict__ in, bf16* __restrict__ out,
                             int K, long long rows) {
    long long idx = (long long)blockIdx.x * 256 + threadIdx.x;   // float4 index
    int K4 = K >> 2;
    long long total4 = rows * K4;
    if (idx >= total4) return;
    long long m = idx / K4;
    int kq = (int)(idx % K4) * 4;
    float4 v = *(const float4*)&in[m * K + kq];
    bf16 h0, l0, h1, l1, h2, l2, h3, l3;
    split2(v.x, h0, l0); split2(v.y, h1, l1);
    split2(v.z, h2, l2); split2(v.w, h3, l3);
    bf16* oh = out + m * (2 * (long long)K) + kq;
    bf16* ol = oh + K;
    oh[0] = h0; oh[1] = h1; oh[2] = h2; oh[3] = h3;
    ol[0] = l0; ol[1] = l1; ol[2] = l2; ol[3] = l3;
}

__global__ void rmsnorm_kernel(const float* __restrict__ x,
                               const float* __restrict__ w,
                               float* __restrict__ o) {
    int t = blockIdx.x;
    const float4* xr = (const float4*)(x + (size_t)t * HH);
    const float4* wr = (const float4*)w;
    float4 xv = xr[threadIdx.x];
    float s = xv.x * xv.x + xv.y * xv.y + xv.z * xv.z + xv.w * xv.w;
    __shared__ float red[256];
    red[threadIdx.x] = s;
    __syncthreads();
    for (int k = 128; k > 0; k >>= 1) {
        if (threadIdx.x < k) red[threadIdx.x] += red[threadIdx.x + k];
        __syncthreads();
    }
    float rs = rsqrtf(red[0] / (float)HH + EPSV);
    float4 wv = wr[threadIdx.x];
    float4 ov = make_float4(xv.x * rs * wv.x, xv.y * rs * wv.y,
                            xv.z * rs * wv.z, xv.w * rs * wv.w);
    ((float4*)(o + (size_t)t * HH))[threadIdx.x] = ov;
}

__global__ void rmsnorm_split_kernel(const float* __restrict__ x,
                                     const float* __restrict__ w,
                                     bf16* __restrict__ o) {
    int t = blockIdx.x;
    const float4* xr = (const float4*)(x + (size_t)t * HH);
    const float4* wr = (const float4*)w;
    float4 xv = xr[threadIdx.x];
    float s = xv.x * xv.x + xv.y * xv.y + xv.z * xv.z + xv.w * xv.w;
    __shared__ float red[256];
    red[threadIdx.x] = s;
    __syncthreads();
    for (int k = 128; k > 0; k >>= 1) {
        if (threadIdx.x < k) red[threadIdx.x] += red[threadIdx.x + k];
        __syncthreads();
    }
    float rs = rsqrtf(red[0] / (float)HH + EPSV);
    float4 wv = wr[threadIdx.x];
    float ov[4] = {xv.x * rs * wv.x, xv.y * rs * wv.y, xv.z * rs * wv.z, xv.w * rs * wv.w};
    bf16* oh = o + (size_t)t * 2 * HH + threadIdx.x * 4;
    bf16* ol = oh + HH;
    #pragma unroll
    for (int i = 0; i < 4; i++) { bf16 hi, lo; split2(ov[i], hi, lo); oh[i] = hi; ol[i] = lo; }
}

__global__ void rope_kernel(float* __restrict__ qkv, const int* __restrict__ positions) {
    int t = blockIdx.x;
    int h = blockIdx.y;
    int d = threadIdx.x;
    int off = (h < NHQ) ? h * HD : NHQ * HD + (h - NHQ) * HD;
    float* p = qkv + (size_t)t * QKVD + off;
    float x1 = p[d];
    float x2 = p[d + 32];
    float pos = (float)positions[t];
    float invf = __expf(-((float)d / 32.0f) * logf(10000.0f));
    float fr = pos * invf;
    float c, s;
    __sincosf(fr, &s, &c);
    p[d]      = x1 * c - x2 * s;
    p[d + 32] = x2 * c + x1 * s;
}

// ---------------- flash attention (fp32), writes bf16 split output ----------------
#define BR 64
#define BC 32
__global__ __launch_bounds__(256) void attn_flash_kernel(
    const float* __restrict__ qkv, bf16* __restrict__ out) {
    int qt = blockIdx.x, h = blockIdx.y;
    int kvh = h >> 2;
    int tid = threadIdx.x;
    int tx = tid & 15, ty = tid >> 4;

    __shared__ float Qs[BR][HD + 1];
    __shared__ float Ks[BC][HD + 1];
    __shared__ float Vs[BC][HD];
    __shared__ float Ps[BR][BC + 1];
    __shared__ float sm[BR], sl[BR], scor[BR];

    for (int i = tid; i < BR * 16; i += 256) {
        int r = i >> 4, c = (i & 15) << 2;
        float4 v = *(const float4*)&qkv[(size_t)(qt * BR + r) * QKVD + h * HD + c];
        Qs[r][c] = v.x; Qs[r][c + 1] = v.y; Qs[r][c + 2] = v.z; Qs[r][c + 3] = v.w;
    }
    if (tid < BR) { sm[tid] = -1e30f; sl[tid] = 0.0f; }

    float acc[4][4] = {};
    int ktmax = (qt * BR + BR - 1) / BC;
    for (int kt = 0; kt <= ktmax; kt++) {
        __syncthreads();
        for (int i = tid; i < BC * 16; i += 256) {
            int r = i >> 4, c = (i & 15) << 2;
            size_t base = (size_t)(kt * BC + r) * QKVD + NHQ * HD + kvh * HD;
            float4 kv = *(const float4*)&qkv[base + c];
            Ks[r][c] = kv.x; Ks[r][c + 1] = kv.y; Ks[r][c + 2] = kv.z; Ks[r][c + 3] = kv.w;
            float4 vv = *(const float4*)&qkv[base + NKVH * HD + c];
            *(float4*)&Vs[r][c] = vv;
        }
        __syncthreads();

        float s[4][2] = {};
        #pragma unroll 8
        for (int d = 0; d < HD; d++) {
            float b0 = Ks[tx * 2][d], b1 = Ks[tx * 2 + 1][d];
            #pragma unroll
            for (int i = 0; i < 4; i++) {
                float a = Qs[ty * 4 + i][d];
                s[i][0] += a * b0;
                s[i][1] += a * b1;
            }
        }
        #pragma unroll
        for (int i = 0; i < 4; i++)
            #pragma unroll
            for (int j = 0; j < 2; j++) {
                int qg = qt * BR + ty * 4 + i;
                int kg = kt * BC + tx * 2 + j;
                Ps[ty * 4 + i][tx * 2 + j] = (kg <= qg) ? s[i][j] * 0.125f : -1e30f;
            }
        __syncthreads();

        if (tid < BR) {
            int r = tid;
            float rm = -1e30f;
            #pragma unroll 8
            for (int j = 0; j < BC; j++) rm = fmaxf(rm, Ps[r][j]);
            float newm = fmaxf(sm[r], rm);
            float corr = __expf(sm[r] - newm);
            float sum = 0.0f;
            #pragma unroll 8
            for (int j = 0; j < BC; j++) {
                float p = __expf(Ps[r][j] - newm);
                Ps[r][j] = p;
                sum += p;
            }
            sl[r] = sl[r] * corr + sum;
            sm[r] = newm;
            scor[r] = corr;
        }
        __syncthreads();

        float c0[4];
        #pragma unroll
        for (int i = 0; i < 4; i++) c0[i] = scor[ty * 4 + i];
        #pragma unroll
        for (int i = 0; i < 4; i++)
            #pragma unroll
            for (int j = 0; j < 4; j++) acc[i][j] *= c0[i];
        #pragma unroll 4
        for (int jj = 0; jj < BC; jj++) {
            float4 b = *(const float4*)&Vs[jj][tx * 4];
            #pragma unroll
            for (int i = 0; i < 4; i++) {
                float a = Ps[ty * 4 + i][jj];
                acc[i][0] += a * b.x; acc[i][1] += a * b.y;
                acc[i][2] += a * b.z; acc[i][3] += a * b.w;
            }
        }
    }

    #pragma unroll
    for (int i = 0; i < 4; i++) {
        int qg = qt * BR + ty * 4 + i;
        float inv = 1.0f / sl[ty * 4 + i];
        bf16* oh = out + (size_t)qg * 2 * HH + h * HD + tx * 4;
        bf16* ol = oh + HH;
        #pragma unroll
        for (int j = 0; j < 4; j++) {
            bf16 hi, lo;
            split2(acc[i][j] * inv, hi, lo);
            oh[j] = hi; ol[j] = lo;
        }
    }
}

// ---------------- bf16 tensor-core GEMM: C = A(Mx K2) * B(N x K2)^T (+Dadd) ----------------
__device__ __forceinline__ void bgemm128(const bf16* __restrict__ A,
                                         const bf16* __restrict__ B,
                                         float* __restrict__ C,
                                         const float* __restrict__ Dadd,
                                         int M, int N, int K2) {
    __shared__ __align__(16) bf16 As[2][128][40];
    __shared__ __align__(16) bf16 Bs[2][128][40];
    const int tid = threadIdx.x;
    const int lane = tid & 31;
    const int wid = tid >> 5;
    const int warp_m = (wid >> 2) * 64;
    const int warp_n = (wid & 3) * 32;
    const int row0 = blockIdx.y * 128;
    const int col0 = blockIdx.x * 128;

    const int lr = tid >> 1;
    const int lc = (tid & 1) * 8;
    int arow = row0 + lr; if (arow >= M) arow = M - 1;
    const bf16* aptr = A + (size_t)arow * K2 + lc;
    const bf16* bptr = B + (size_t)(col0 + lr) * K2 + lc;

    float acc[4][4][4] = {};

    float4 av0 = *(const float4*)aptr;
    float4 av1 = *(const float4*)(aptr + 16);
    float4 bv0 = *(const float4*)bptr;
    float4 bv1 = *(const float4*)(bptr + 16);
    *(float4*)&As[0][lr][lc] = av0; *(float4*)&As[0][lr][lc + 16] = av1;
    *(float4*)&Bs[0][lr][lc] = bv0; *(float4*)&Bs[0][lr][lc + 16] = bv1;
    __syncthreads();

    const int nt = K2 >> 5;
    const int r  = lane >> 2;
    const int tq = (lane & 3) * 2;
    for (int kt = 0; kt < nt; kt++) {
        int cur = kt & 1;
        if (kt + 1 < nt) {
            const bf16* ap = aptr + (kt + 1) * 32;
            const bf16* bp = bptr + (kt + 1) * 32;
            av0 = *(const float4*)ap; av1 = *(const float4*)(ap + 16);
            bv0 = *(const float4*)bp; bv1 = *(const float4*)(bp + 16);
        }
        #pragma unroll
        for (int ks = 0; ks < 2; ks++) {
            const int kb = ks * 16;
            uint32_t afr[4][4], bfr[4][2];
            #pragma unroll
            for (int mt = 0; mt < 4; mt++) {
                int rb = warp_m + mt * 16 + r;
                afr[mt][0] = *(const uint32_t*)&As[cur][rb][kb + tq];
                afr[mt][1] = *(const uint32_t*)&As[cur][rb + 8][kb + tq];
                afr[mt][2] = *(const uint32_t*)&As[cur][rb][kb + tq + 8];
                afr[mt][3] = *(const uint32_t*)&As[cur][rb + 8][kb + tq + 8];
            }
            #pragma unroll
            for (int nn = 0; nn < 4; nn++) {
                int nb = warp_n + nn * 8 + r;
                bfr[nn][0] = *(const uint32_t*)&Bs[cur][nb][kb + tq];
                bfr[nn][1] = *(const uint32_t*)&Bs[cur][nb][kb + tq + 8];
            }
            #pragma unroll
            for (int mt = 0; mt < 4; mt++)
                #pragma unroll
                for (int nn = 0; nn < 4; nn++)
                    mma16816(acc[mt][nn], afr[mt], bfr[nn]);
        }
        if (kt + 1 < nt) {
            int nb = cur ^ 1;
            *(float4*)&As[nb][lr][lc] = av0; *(float4*)&As[nb][lr][lc + 16] = av1;
            *(float4*)&Bs[nb][lr][lc] = bv0; *(float4*)&Bs[nb][lr][lc + 16] = bv1;
        }
        __syncthreads();
    }

    #pragma unroll
    for (int mt = 0; mt < 4; mt++) {
        #pragma unroll
        for (int nn = 0; nn < 4; nn++) {
            int rr0 = row0 + warp_m + mt * 16 + r;
            int cc  = col0 + warp_n + nn * 8 + tq;
            if (rr0 < M) {
                float2 v = make_float2(acc[mt][nn][0], acc[mt][nn][1]);
                if (Dadd) {
                    v.x += Dadd[(size_t)rr0 * N + cc];
                    v.y += Dadd[(size_t)rr0 * N + cc + 1];
                }
                *(float2*)&C[(size_t)rr0 * N + cc] = v;
            }
            int rr1 = rr0 + 8;
            if (rr1 < M) {
                float2 v = make_float2(acc[mt][nn][2], acc[mt][nn][3]);
                if (Dadd) {
                    v.x += Dadd[(size_t)rr1 * N + cc];
                    v.y += Dadd[(size_t)rr1 * N + cc + 1];
                }
                *(float2*)&C[(size_t)rr1 * N + cc] = v;
            }
        }
    }
}

__global__ __launch_bounds__(256) void bgemm_nt_kernel(
    const bf16* A, const bf16* B, float* C, const float* Dadd, int M, int N, int K2) {
    bgemm128(A, B, C, Dadd, M, N, K2);
}

__global__ __launch_bounds__(256) void bgemm_grouped_kernel(
    const bf16* A, const bf16* B, float* C, int N, int K2,
    long long Asl, long long Bsl, long long Csl) {
    int e = blockIdx.z;
    int M = g_cnt[e];
    if ((int)blockIdx.y * 128 >= M) return;
    bgemm128(A + (size_t)e * Asl, B + (size_t)e * Bsl, C + (size_t)e * Csl,
             nullptr, M, N, K2);
}

// ---------------- silu_and_mul (writes bf16 split) ----------------
__global__ void silu_split_kernel(const float* __restrict__ gu, bf16* __restrict__ o) {
    int t = blockIdx.x;
    const float4* g = (const float4*)(gu + (size_t)t * 2 * HH);
    const float4* u = (const float4*)(gu + (size_t)t * 2 * HH + HH);
    float4 gv = g[threadIdx.x], uv = u[threadIdx.x];
    float r[4];
    r[0] = gv.x / (1.0f + __expf(-gv.x)) * uv.x;
    r[1] = gv.y / (1.0f + __expf(-gv.y)) * uv.y;
    r[2] = gv.z / (1.0f + __expf(-gv.z)) * uv.z;
    r[3] = gv.w / (1.0f + __expf(-gv.w)) * uv.w;
    bf16* oh = o + (size_t)t * 2 * HH + threadIdx.x * 4;
    bf16* ol = oh + HH;
    #pragma unroll
    for (int i = 0; i < 4; i++) { bf16 hi, lo; split2(r[i], hi, lo); oh[i] = hi; ol[i] = lo; }
}

__global__ void silu_grouped_kernel() {
    int e = blockIdx.y, rr = blockIdx.x;
    if (rr >= g_cnt[e]) return;
    const float4* g = (const float4*)(g_gu + ((size_t)e * TT + rr) * (2 * NI));
    const float4* u = (const float4*)(g_gu + ((size_t)e * TT + rr) * (2 * NI) + NI);
    bf16* oh = s_act + ((size_t)e * TT + rr) * (2 * NI);
    bf16* ol = oh + NI;
    for (int i = threadIdx.x; i < NI / 4; i += 256) {
        float4 gv = g[i], uv = u[i];
        float r[4];
        r[0] = gv.x / (1.0f + __expf(-gv.x)) * uv.x;
        r[1] = gv.y / (1.0f + __expf(-gv.y)) * uv.y;
        r[2] = gv.z / (1.0f + __expf(-gv.z)) * uv.z;
        r[3] = gv.w / (1.0f + __expf(-gv.w)) * uv.w;
        #pragma unroll
        for (int j = 0; j < 4; j++) {
            bf16 hi, lo; split2(r[j], hi, lo);
            oh[i * 4 + j] = hi; ol[i * 4 + j] = lo;
        }
    }
}

// ---------------- MoE routing ----------------
__global__ void gate_kernel(const float* __restrict__ m, const float* __restrict__ gw) {
    int t = blockIdx.x;
    __shared__ float logits[NE];
    int warp = threadIdx.x >> 5, lane = threadIdx.x & 31;
    const float* xr = m + (size_t)t * HH;
    const float* wr = gw + (size_t)warp * HH;
    float s = 0.0f;
    for (int i = lane; i < HH; i += 32) s += xr[i] * wr[i];
    for (int o = 16; o > 0; o >>= 1) s += __shfl_down_sync(0xffffffffu, s, o);
    if (lane == 0) logits[warp] = s;
    __syncthreads();
    if (threadIdx.x == 0) {
        float mx = logits[0];
        for (int e = 1; e < NE; e++) mx = fmaxf(mx, logits[e]);
        float p[NE]; float sum = 0.0f;
        for (int e = 0; e < NE; e++) { p[e] = __expf(logits[e] - mx); sum += p[e]; }
        for (int e = 0; e < NE; e++) p[e] /= sum;
        int i0 = 0;
        for (int e = 1; e < NE; e++) if (p[e] > p[i0]) i0 = e;
        int i1 = (i0 == 0) ? 1 : 0;
        for (int e = 0; e < NE; e++) if (e != i0 && p[e] > p[i1]) i1 = e;
        float inv = 1.0f / (p[i0] + p[i1]);
        int pos0 = atomicAdd(&g_cnt[i0], 1);
        g_tok[i0 * TT + pos0] = t; g_wt[i0 * TT + pos0] = p[i0] * inv;
        int pos1 = atomicAdd(&g_cnt[i1], 1);
        g_tok[i1 * TT + pos1] = t; g_wt[i1 * TT + pos1] = p[i1] * inv;
    }
}

__global__ void gather_split_kernel(const float* __restrict__ m) {
    int e = blockIdx.y, rr = blockIdx.x;
    if (rr >= g_cnt[e]) return;
    int t = g_tok[e * TT + rr];
    float4 v = ((const float4*)(m + (size_t)t * HH))[threadIdx.x];
    bf16* oh = s_xe + ((size_t)e * TT + rr) * 2 * HH + threadIdx.x * 4;
    bf16* ol = oh + HH;
    float r[4] = {v.x, v.y, v.z, v.w};
    #pragma unroll
    for (int i = 0; i < 4; i++) { bf16 hi, lo; split2(r[i], hi, lo); oh[i] = hi; ol[i] = lo; }
}

__global__ void scatter_kernel(float* __restrict__ out) {
    int e = blockIdx.y, rr = blockIdx.x;
    if (rr >= g_cnt[e]) return;
    int t = g_tok[e * TT + rr];
    float w = g_wt[e * TT + rr];
    const float* src = g_eo + ((size_t)e * TT + rr) * HH;
    float* dst = out + (size_t)t * HH;
    for (int i = threadIdx.x; i < HH; i += 256) atomicAdd(&dst[i], w * src[i]);
}

// ---------------- launch ----------------
static inline int grid4(long long elems) { return (int)((elems / 4 + 255) / 256); }

extern "C" void kernel_launch(void* const* d_in, const int* in_sizes, int n_in,
                              void* d_out, int out_size) {
    (void)in_sizes; (void)n_in; (void)out_size;
    const int*   positions = (const int*)  d_in[0];
    const float* hidden    = (const float*)d_in[1];
    const float* input_ln  = (const float*)d_in[2];
    const float* post_ln   = (const float*)d_in[3];
    const float* resid_ln  = (const float*)d_in[4];
    const float* qkv_w     = (const float*)d_in[5];
    const float* o_w       = (const float*)d_in[6];
    const float* gate_w    = (const float*)d_in[7];
    const float* ws        = (const float*)d_in[8];
    const float* w2s       = (const float*)d_in[9];
    const float* w13       = (const float*)d_in[10];
    const float* w2        = (const float*)d_in[11];
    float* out = (float*)d_out;

    float *p_qkv, *p_resattn, *p_gu13, *p_rmlp, *p_m, *p_gu, *p_eo;
    bf16 *p_sh, *p_sattn, *p_ssilu, *p_sqkvw, *p_sow, *p_sw13, *p_sw2, *p_sws, *p_sw2s, *p_sxe, *p_sact;
    cudaGetSymbolAddress((void**)&p_qkv,     g_qkv);
    cudaGetSymbolAddress((void**)&p_resattn, g_resattn);
    cudaGetSymbolAddress((void**)&p_gu13,    g_gu13);
    cudaGetSymbolAddress((void**)&p_rmlp,    g_rmlp);
    cudaGetSymbolAddress((void**)&p_m,       g_m);
    cudaGetSymbolAddress((void**)&p_gu,      g_gu);
    cudaGetSymbolAddress((void**)&p_eo,      g_eo);
    cudaGetSymbolAddress((void**)&p_sh,      s_h);
    cudaGetSymbolAddress((void**)&p_sattn,   s_attn);
    cudaGetSymbolAddress((void**)&p_ssilu,   s_silu);
    cudaGetSymbolAddress((void**)&p_sqkvw,   s_qkvw);
    cudaGetSymbolAddress((void**)&p_sow,     s_ow);
    cudaGetSymbolAddress((void**)&p_sw13,    s_w13);
    cudaGetSymbolAddress((void**)&p_sw2,     s_w2);
    cudaGetSymbolAddress((void**)&p_sws,     s_ws);
    cudaGetSymbolAddress((void**)&p_sw2s,    s_w2s);
    cudaGetSymbolAddress((void**)&p_sxe,     s_xe);
    cudaGetSymbolAddress((void**)&p_sact,    s_act);

    zero_cnt_kernel<<<1, 32>>>();

    // weight splits
    split_kernel<<<grid4((long long)QKVD * HH), 256>>>(qkv_w, p_sqkvw, HH, QKVD);
    split_kernel<<<grid4((long long)HH * HH), 256>>>(o_w, p_sow, HH, HH);
    split_kernel<<<grid4((long long)2 * HH * HH), 256>>>(w13, p_sw13, HH, 2 * HH);
    split_kernel<<<grid4((long long)HH * HH), 256>>>(w2, p_sw2, HH, HH);
    split_kernel<<<grid4((long long)NE * 2 * NI * HH), 256>>>(ws, p_sws, HH, (long long)NE * 2 * NI);
    split_kernel<<<grid4((long long)NE * HH * NI), 256>>>(w2s, p_sw2s, NI, (long long)NE * HH);

    // h = rms_norm(hidden, input_ln_w)  (bf16 split)
    rmsnorm_split_kernel<<<TT, 256>>>(hidden, input_ln, p_sh);

    // qkv = h @ qkv_w.T
    bgemm_nt_kernel<<<dim3(QKVD / 128, TT / 128), 256>>>(p_sh, p_sqkvw, p_qkv, nullptr, TT, QKVD, 2 * HH);

    rope_kernel<<<dim3(TT, NHQ + NKVH), 32>>>(p_qkv, positions);

    attn_flash_kernel<<<dim3(TT / BR, NHQ), 256>>>(p_qkv, p_sattn);

    // residual_attn = hidden + attn @ o_w.T
    bgemm_nt_kernel<<<dim3(HH / 128, TT / 128), 256>>>(p_sattn, p_sow, p_resattn, hidden, TT, HH, 2 * HH);

    // residual MLP
    rmsnorm_split_kernel<<<TT, 256>>>(p_resattn, resid_ln, p_sh);
    bgemm_nt_kernel<<<dim3(2 * HH / 128, TT / 128), 256>>>(p_sh, p_sw13, p_gu13, nullptr, TT, 2 * HH, 2 * HH);
    silu_split_kernel<<<TT, 256>>>(p_gu13, p_ssilu);
    bgemm_nt_kernel<<<dim3(HH / 128, TT / 128), 256>>>(p_ssilu, p_sw2, p_rmlp, p_resattn, TT, HH, 2 * HH);

    // out starts as residual_mlp; MoE scatters into it
    cudaMemcpyAsync(out, p_rmlp, (size_t)TT * HH * sizeof(float), cudaMemcpyDeviceToDevice);

    // MoE
    rmsnorm_kernel<<<TT, 256>>>(p_resattn, post_ln, p_m);
    gate_kernel<<<TT, 256>>>(p_m, gate_w);
    gather_split_kernel<<<dim3(TT, NE), 256>>>(p_m);
    bgemm_grouped_kernel<<<dim3(2 * NI / 128, TT / 128, NE), 256>>>(
        p_sxe, p_sws, p_gu, 2 * NI, 2 * HH,
        (long long)TT * 2 * HH, (long long)2 * NI * 2 * HH, (long long)TT * 2 * NI);
    silu_grouped_kernel<<<dim3(TT, NE), 256>>>();
    bgemm_grouped_kernel<<<dim3(HH / 128, TT / 128, NE), 256>>>(
        p_sact, p_sw2s, p_eo, HH, 2 * NI,
        (long long)TT * 2 * NI, (long long)HH * 2 * NI, (long long)TT * HH);
    scatter_kernel<<<dim3(TT, NE), 256>>>(out);
}

// round 4
// speedup vs baseline: 7.8805x; 1.0956x over previous
#include <cuda_runtime.h>
#include <cuda_fp16.h>
#include <math.h>
#include <stdint.h>

#define TT   2048
#define HH   1024
#define NHQ  16
#define NKVH 4
#define HD   64
#define QKVD ((NHQ + 2*NKVH) * HD)   // 1536
#define NE   8
#define NI   2048
#define EPSV 1e-5f

typedef __half h16;

// ---------------- scratch (device globals; no allocations) ----------------
__device__ float g_qkv    [(size_t)TT * QKVD];
__device__ float g_resattn[(size_t)TT * HH];
__device__ float g_m      [(size_t)TT * HH];
__device__ int   g_cnt    [NE];
__device__ int   g_tok    [NE * TT];
__device__ float g_wt     [NE * TT];

// fp16 split buffers: row-major M x 2K, [hi | lo] along K
__device__ __align__(16) h16 s_h    [(size_t)TT * 2 * HH];
__device__ __align__(16) h16 s_attn [(size_t)TT * 2 * HH];
__device__ __align__(16) h16 s_silu [(size_t)TT * 2 * HH];
__device__ __align__(16) h16 s_qkvw [(size_t)QKVD * 2 * HH];
__device__ __align__(16) h16 s_ow   [(size_t)HH * 2 * HH];
__device__ __align__(16) h16 s_w13i [(size_t)2 * HH * 2 * HH];     // interleaved g/u rows
__device__ __align__(16) h16 s_w2   [(size_t)HH * 2 * HH];
__device__ __align__(16) h16 s_wsi  [(size_t)NE * 2 * NI * 2 * HH]; // interleaved g/u rows
__device__ __align__(16) h16 s_w2s  [(size_t)NE * HH * 2 * NI];
__device__ __align__(16) h16 s_xe   [(size_t)NE * TT * 2 * HH];
__device__ __align__(16) h16 s_act  [(size_t)NE * TT * 2 * NI];

// ---------------- helpers ----------------
__device__ __forceinline__ void split2h(float x, h16& hi, h16& lo) {
    hi = __float2half(x);
    lo = __float2half(x - __half2float(hi));
}

__device__ __forceinline__ void mma16816(float* c, const uint32_t* a, const uint32_t* b) {
    asm volatile(
        "mma.sync.aligned.m16n8k16.row.col.f32.f16.f16.f32 "
        "{%0,%1,%2,%3}, {%4,%5,%6,%7}, {%8,%9}, {%0,%1,%2,%3};"
        : "+f"(c[0]), "+f"(c[1]), "+f"(c[2]), "+f"(c[3])
        : "r"(a[0]), "r"(a[1]), "r"(a[2]), "r"(a[3]), "r"(b[0]), "r"(b[1]));
}

// ---------------- utility kernels ----------------
__global__ void zero_cnt_kernel() {
    if (threadIdx.x < NE) g_cnt[threadIdx.x] = 0;
}

// fp32 -> fp16 split (rows x K -> rows x 2K)
__global__ void split_kernel(const float* __restrict__ in, h16* __restrict__ out,
                             int K, long long rows) {
    long long idx = (long long)blockIdx.x * 256 + threadIdx.x;
    int K4 = K >> 2;
    long long total4 = rows * K4;
    if (idx >= total4) return;
    long long m = idx / K4;
    int kq = (int)(idx % K4) * 4;
    float4 v = *(const float4*)&in[m * K + kq];
    h16* oh = out + m * (2 * (long long)K) + kq;
    h16* ol = oh + K;
    h16 hi, lo;
    split2h(v.x, hi, lo); oh[0] = hi; ol[0] = lo;
    split2h(v.y, hi, lo); oh[1] = hi; ol[1] = lo;
    split2h(v.z, hi, lo); oh[2] = hi; ol[2] = lo;
    split2h(v.w, hi, lo); oh[3] = hi; ol[3] = lo;
}

// fp32 -> fp16 split with gate/up row interleave:
// input rows per group = 2*I (gate rows [0,I), up rows [I,2I)); out row 2j<-j, 2j+1<-I+j
__global__ void split_interleave_kernel(const float* __restrict__ in, h16* __restrict__ out,
                                        int K, int I, int groups) {
    long long idx = (long long)blockIdx.x * 256 + threadIdx.x;
    int K4 = K >> 2;
    long long per_group = (long long)2 * I * K4;
    long long total4 = (long long)groups * per_group;
    if (idx >= total4) return;
    int g = (int)(idx / per_group);
    long long rem = idx % per_group;
    int r = (int)(rem / K4);
    int kq = (int)(rem % K4) * 4;
    int outr = (r < I) ? (2 * r) : (2 * (r - I) + 1);
    float4 v = *(const float4*)&in[((size_t)g * 2 * I + r) * K + kq];
    h16* oh = out + ((size_t)g * 2 * I + outr) * (2 * (long long)K) + kq;
    h16* ol = oh + K;
    h16 hi, lo;
    split2h(v.x, hi, lo); oh[0] = hi; ol[0] = lo;
    split2h(v.y, hi, lo); oh[1] = hi; ol[1] = lo;
    split2h(v.z, hi, lo); oh[2] = hi; ol[2] = lo;
    split2h(v.w, hi, lo); oh[3] = hi; ol[3] = lo;
}

__global__ void rmsnorm_kernel(const float* __restrict__ x,
                               const float* __restrict__ w,
                               float* __restrict__ o) {
    int t = blockIdx.x;
    float4 xv = ((const float4*)(x + (size_t)t * HH))[threadIdx.x];
    float s = xv.x * xv.x + xv.y * xv.y + xv.z * xv.z + xv.w * xv.w;
    __shared__ float red[256];
    red[threadIdx.x] = s;
    __syncthreads();
    for (int k = 128; k > 0; k >>= 1) {
        if (threadIdx.x < k) red[threadIdx.x] += red[threadIdx.x + k];
        __syncthreads();
    }
    float rs = rsqrtf(red[0] / (float)HH + EPSV);
    float4 wv = ((const float4*)w)[threadIdx.x];
    ((float4*)(o + (size_t)t * HH))[threadIdx.x] =
        make_float4(xv.x * rs * wv.x, xv.y * rs * wv.y, xv.z * rs * wv.z, xv.w * rs * wv.w);
}

__global__ void rmsnorm_split_kernel(const float* __restrict__ x,
                                     const float* __restrict__ w,
                                     h16* __restrict__ o) {
    int t = blockIdx.x;
    float4 xv = ((const float4*)(x + (size_t)t * HH))[threadIdx.x];
    float s = xv.x * xv.x + xv.y * xv.y + xv.z * xv.z + xv.w * xv.w;
    __shared__ float red[256];
    red[threadIdx.x] = s;
    __syncthreads();
    for (int k = 128; k > 0; k >>= 1) {
        if (threadIdx.x < k) red[threadIdx.x] += red[threadIdx.x + k];
        __syncthreads();
    }
    float rs = rsqrtf(red[0] / (float)HH + EPSV);
    float4 wv = ((const float4*)w)[threadIdx.x];
    float ov[4] = {xv.x * rs * wv.x, xv.y * rs * wv.y, xv.z * rs * wv.z, xv.w * rs * wv.w};
    h16* oh = o + (size_t)t * 2 * HH + threadIdx.x * 4;
    h16* ol = oh + HH;
    #pragma unroll
    for (int i = 0; i < 4; i++) { h16 hi, lo; split2h(ov[i], hi, lo); oh[i] = hi; ol[i] = lo; }
}

__global__ void rope_kernel(float* __restrict__ qkv, const int* __restrict__ positions) {
    int idx = blockIdx.x * 256 + threadIdx.x;
    if (idx >= TT * (NHQ + NKVH) * 32) return;
    int t = idx / ((NHQ + NKVH) * 32);
    int rem = idx % ((NHQ + NKVH) * 32);
    int h = rem >> 5;
    int d = rem & 31;
    int off = (h < NHQ) ? h * HD : NHQ * HD + (h - NHQ) * HD;
    float* p = qkv + (size_t)t * QKVD + off;
    float x1 = p[d];
    float x2 = p[d + 32];
    float pos = (float)positions[t];
    float invf = __expf(-0.2878231366f * (float)d);   // ln(10000)/32
    float fr = pos * invf;
    float c, s;
    __sincosf(fr, &s, &c);
    p[d]      = x1 * c - x2 * s;
    p[d + 32] = x2 * c + x1 * s;
}

// ---------------- tensor-core flash attention: 64x64 tiles ----------------
// smem layout (dynamic):
//   QsH [64][136] h16  (hi cols 0..63, lo 64..127, pad to 136)
//   KsH [64][136] h16
//   VsH [64][136] h16  (transposed: row=d, cols=j hi / j+64 lo)
//   PsH [64][136] h16
//   Ss  [64][66]  f32
//   sm/sl/sc [64] f32 each
#define ATT_SMEM (4 * 64 * 136 * 2 + 64 * 66 * 4 + 3 * 64 * 4)

__global__ __launch_bounds__(256) void attn_mma_kernel(
    const float* __restrict__ qkv, h16* __restrict__ outH) {
    extern __shared__ char smraw[];
    h16*  QsH = (h16*)smraw;
    h16*  KsH = QsH + 64 * 136;
    h16*  VsH = KsH + 64 * 136;
    h16*  PsH = VsH + 64 * 136;
    float* Ss  = (float*)(PsH + 64 * 136);
    float* sm_s = Ss + 64 * 66;
    float* sl_s = sm_s + 64;
    float* sc_s = sl_s + 64;

    int qt = blockIdx.x, h = blockIdx.y;
    int kvh = h >> 2;
    int tid = threadIdx.x, lane = tid & 31, wid = tid >> 5;
    int warp_m = (wid >> 1) * 16, warp_n = (wid & 1) * 32;
    int r = lane >> 2, tq = (lane & 3) * 2;

    // load + split Q tile
    for (int i = tid; i < 64 * 16; i += 256) {
        int row = i >> 4, c = (i & 15) << 2;
        float4 v = *(const float4*)&qkv[(size_t)(qt * 64 + row) * QKVD + h * HD + c];
        h16 hi, lo;
        h16* qh = QsH + row * 136 + c;
        split2h(v.x, hi, lo); qh[0] = hi; qh[64] = lo;
        split2h(v.y, hi, lo); qh[1] = hi; qh[65] = lo;
        split2h(v.z, hi, lo); qh[2] = hi; qh[66] = lo;
        split2h(v.w, hi, lo); qh[3] = hi; qh[67] = lo;
    }
    if (tid < 64) { sm_s[tid] = -1e30f; sl_s[tid] = 0.0f; }

    float oacc[4][4] = {};
    for (int kt = 0; kt <= qt; kt++) {
        __syncthreads();   // protect K/V/P reuse + initial stats
        // load + split K, V (V transposed)
        for (int i = tid; i < 64 * 16; i += 256) {
            int row = i >> 4, c = (i & 15) << 2;
            size_t base = (size_t)(kt * 64 + row) * QKVD + NHQ * HD + kvh * HD;
            float4 kv = *(const float4*)&qkv[base + c];
            h16 hi, lo;
            h16* kp = KsH + row * 136 + c;
            split2h(kv.x, hi, lo); kp[0] = hi; kp[64] = lo;
            split2h(kv.y, hi, lo); kp[1] = hi; kp[65] = lo;
            split2h(kv.z, hi, lo); kp[2] = hi; kp[66] = lo;
            split2h(kv.w, hi, lo); kp[3] = hi; kp[67] = lo;
            float4 vv = *(const float4*)&qkv[base + NKVH * HD + c];
            split2h(vv.x, hi, lo); VsH[(c + 0) * 136 + row] = hi; VsH[(c + 0) * 136 + 64 + row] = lo;
            split2h(vv.y, hi, lo); VsH[(c + 1) * 136 + row] = hi; VsH[(c + 1) * 136 + 64 + row] = lo;
            split2h(vv.z, hi, lo); VsH[(c + 2) * 136 + row] = hi; VsH[(c + 2) * 136 + 64 + row] = lo;
            split2h(vv.w, hi, lo); VsH[(c + 3) * 136 + row] = hi; VsH[(c + 3) * 136 + 64 + row] = lo;
        }
        __syncthreads();

        // S = Q @ K^T  (K' = 128 split dims)
        float sacc[4][4] = {};
        #pragma unroll
        for (int kb = 0; kb < 8; kb++) {
            int kbo = kb * 16;
            uint32_t af[4];
            af[0] = *(const uint32_t*)&QsH[(warp_m + r) * 136 + kbo + tq];
            af[1] = *(const uint32_t*)&QsH[(warp_m + r + 8) * 136 + kbo + tq];
            af[2] = *(const uint32_t*)&QsH[(warp_m + r) * 136 + kbo + tq + 8];
            af[3] = *(const uint32_t*)&QsH[(warp_m + r + 8) * 136 + kbo + tq + 8];
            #pragma unroll
            for (int nn = 0; nn < 4; nn++) {
                uint32_t bf[2];
                bf[0] = *(const uint32_t*)&KsH[(warp_n + nn * 8 + r) * 136 + kbo + tq];
                bf[1] = *(const uint32_t*)&KsH[(warp_n + nn * 8 + r) * 136 + kbo + tq + 8];
                mma16816(sacc[nn], af, bf);
            }
        }
        #pragma unroll
        for (int nn = 0; nn < 4; nn++) {
            int col = warp_n + nn * 8 + tq;
            *(float2*)&Ss[(warp_m + r) * 66 + col]     = make_float2(sacc[nn][0], sacc[nn][1]);
            *(float2*)&Ss[(warp_m + r + 8) * 66 + col] = make_float2(sacc[nn][2], sacc[nn][3]);
        }
        __syncthreads();

        // online softmax: 4 threads per row
        {
            int row = tid >> 2, sub = tid & 3;
            float rm = -1e30f;
            #pragma unroll
            for (int jj = 0; jj < 16; jj++) {
                int j = sub * 16 + jj;
                float s = Ss[row * 66 + j] * 0.125f;
                if (kt == qt && j > row) s = -1e30f;
                Ss[row * 66 + j] = s;
                rm = fmaxf(rm, s);
            }
            rm = fmaxf(rm, __shfl_xor_sync(0xffffffffu, rm, 1));
            rm = fmaxf(rm, __shfl_xor_sync(0xffffffffu, rm, 2));
            float oldm = sm_s[row];
            float newm = fmaxf(oldm, rm);
            float sum = 0.0f;
            #pragma unroll
            for (int jj = 0; jj < 16; jj++) {
                int j = sub * 16 + jj;
                float p = __expf(Ss[row * 66 + j] - newm);
                sum += p;
                h16 hi, lo;
                split2h(p, hi, lo);
                PsH[row * 136 + j] = hi;
                PsH[row * 136 + 64 + j] = lo;
            }
            sum += __shfl_xor_sync(0xffffffffu, sum, 1);
            sum += __shfl_xor_sync(0xffffffffu, sum, 2);
            if (sub == 0) {
                float corr = __expf(oldm - newm);
                sl_s[row] = sl_s[row] * corr + sum;
                sc_s[row] = corr;
                sm_s[row] = newm;
            }
        }
        __syncthreads();

        // O = O*corr + P @ V
        float c0 = sc_s[warp_m + r], c1 = sc_s[warp_m + r + 8];
        #pragma unroll
        for (int nn = 0; nn < 4; nn++) {
            oacc[nn][0] *= c0; oacc[nn][1] *= c0;
            oacc[nn][2] *= c1; oacc[nn][3] *= c1;
        }
        #pragma unroll
        for (int kb = 0; kb < 8; kb++) {
            int kbo = kb * 16;
            uint32_t af[4];
            af[0] = *(const uint32_t*)&PsH[(warp_m + r) * 136 + kbo + tq];
            af[1] = *(const uint32_t*)&PsH[(warp_m + r + 8) * 136 + kbo + tq];
            af[2] = *(const uint32_t*)&PsH[(warp_m + r) * 136 + kbo + tq + 8];
            af[3] = *(const uint32_t*)&PsH[(warp_m + r + 8) * 136 + kbo + tq + 8];
            #pragma unroll
            for (int nn = 0; nn < 4; nn++) {
                uint32_t bf[2];
                bf[0] = *(const uint32_t*)&VsH[(warp_n + nn * 8 + r) * 136 + kbo + tq];
                bf[1] = *(const uint32_t*)&VsH[(warp_n + nn * 8 + r) * 136 + kbo + tq + 8];
                mma16816(oacc[nn], af, bf);
            }
        }
    }

    // epilogue: normalize, split, store
    float inv0 = 1.0f / sl_s[warp_m + r];
    float inv1 = 1.0f / sl_s[warp_m + r + 8];
    int q0 = qt * 64 + warp_m + r;
    int q1 = q0 + 8;
    #pragma unroll
    for (int nn = 0; nn < 4; nn++) {
        int d0 = h * HD + warp_n + nn * 8 + tq;
        h16 hi, lo;
        split2h(oacc[nn][0] * inv0, hi, lo);
        outH[(size_t)q0 * 2 * HH + d0] = hi;      outH[(size_t)q0 * 2 * HH + HH + d0] = lo;
        split2h(oacc[nn][1] * inv0, hi, lo);
        outH[(size_t)q0 * 2 * HH + d0 + 1] = hi;  outH[(size_t)q0 * 2 * HH + HH + d0 + 1] = lo;
        split2h(oacc[nn][2] * inv1, hi, lo);
        outH[(size_t)q1 * 2 * HH + d0] = hi;      outH[(size_t)q1 * 2 * HH + HH + d0] = lo;
        split2h(oacc[nn][3] * inv1, hi, lo);
        outH[(size_t)q1 * 2 * HH + d0 + 1] = hi;  outH[(size_t)q1 * 2 * HH + HH + d0 + 1] = lo;
    }
}

// ---------------- fp16 tensor-core GEMM, templated epilogue ----------------
// MODE 0: Cf = A*B^T (+ Dadd if non-null)
// MODE 1: pairs (even,odd) cols = (g,u) -> silu(g)*u, fp16 split into OutH (half-width halfW)
// MODE 2: atomicAdd(OutAtom[tok[row]*N + col] += wt[row]*val)   (grouped MoE down-proj)
template<int MODE>
__global__ __launch_bounds__(256) void gemm_kernel(
    const h16* __restrict__ Aall, const h16* __restrict__ Ball,
    float* __restrict__ Cf, const float* __restrict__ Dadd,
    h16* __restrict__ OutH, int halfW,
    float* __restrict__ OutAtom,
    int M0, int N, int K2,
    long long Asl, long long Bsl, long long OslH) {

    int e = (gridDim.z > 1) ? blockIdx.z : 0;
    int M = (gridDim.z > 1) ? g_cnt[e] : M0;
    if ((int)blockIdx.y * 128 >= M) return;
    const h16* A = Aall + (size_t)e * Asl;
    const h16* B = Ball + (size_t)e * Bsl;

    __shared__ __align__(16) h16 As[2][128][40];
    __shared__ __align__(16) h16 Bs[2][128][40];
    const int tid = threadIdx.x;
    const int lane = tid & 31;
    const int wid = tid >> 5;
    const int warp_m = (wid >> 2) * 64;
    const int warp_n = (wid & 3) * 32;
    const int row0 = blockIdx.y * 128;
    const int col0 = blockIdx.x * 128;

    const int lr = tid >> 1;
    const int lc = (tid & 1) * 8;
    int arow = row0 + lr; if (arow >= M) arow = M - 1;
    const h16* aptr = A + (size_t)arow * K2 + lc;
    const h16* bptr = B + (size_t)(col0 + lr) * K2 + lc;

    float acc[4][4][4] = {};

    float4 av0 = *(const float4*)aptr;
    float4 av1 = *(const float4*)(aptr + 16);
    float4 bv0 = *(const float4*)bptr;
    float4 bv1 = *(const float4*)(bptr + 16);
    *(float4*)&As[0][lr][lc] = av0; *(float4*)&As[0][lr][lc + 16] = av1;
    *(float4*)&Bs[0][lr][lc] = bv0; *(float4*)&Bs[0][lr][lc + 16] = bv1;
    __syncthreads();

    const int nt = K2 >> 5;
    const int r  = lane >> 2;
    const int tq = (lane & 3) * 2;
    for (int kt = 0; kt < nt; kt++) {
        int cur = kt & 1;
        if (kt + 1 < nt) {
            const h16* ap = aptr + (kt + 1) * 32;
            const h16* bp = bptr + (kt + 1) * 32;
            av0 = *(const float4*)ap; av1 = *(const float4*)(ap + 16);
            bv0 = *(const float4*)bp; bv1 = *(const float4*)(bp + 16);
        }
        #pragma unroll
        for (int ks = 0; ks < 2; ks++) {
            const int kb = ks * 16;
            uint32_t afr[4][4], bfr[4][2];
            #pragma unroll
            for (int mt = 0; mt < 4; mt++) {
                int rb = warp_m + mt * 16 + r;
                afr[mt][0] = *(const uint32_t*)&As[cur][rb][kb + tq];
                afr[mt][1] = *(const uint32_t*)&As[cur][rb + 8][kb + tq];
                afr[mt][2] = *(const uint32_t*)&As[cur][rb][kb + tq + 8];
                afr[mt][3] = *(const uint32_t*)&As[cur][rb + 8][kb + tq + 8];
            }
            #pragma unroll
            for (int nn = 0; nn < 4; nn++) {
                int nb = warp_n + nn * 8 + r;
                bfr[nn][0] = *(const uint32_t*)&Bs[cur][nb][kb + tq];
                bfr[nn][1] = *(const uint32_t*)&Bs[cur][nb][kb + tq + 8];
            }
            #pragma unroll
            for (int mt = 0; mt < 4; mt++)
                #pragma unroll
                for (int nn = 0; nn < 4; nn++)
                    mma16816(acc[mt][nn], afr[mt], bfr[nn]);
        }
        if (kt + 1 < nt) {
            int nb = cur ^ 1;
            *(float4*)&As[nb][lr][lc] = av0; *(float4*)&As[nb][lr][lc + 16] = av1;
            *(float4*)&Bs[nb][lr][lc] = bv0; *(float4*)&Bs[nb][lr][lc + 16] = bv1;
        }
        __syncthreads();
    }

    const int* tok = g_tok + e * TT;
    const float* wt = g_wt + e * TT;
    h16* outh = (MODE == 1) ? (OutH + (size_t)e * OslH) : OutH;

    #pragma unroll
    for (int mt = 0; mt < 4; mt++) {
        #pragma unroll
        for (int nn = 0; nn < 4; nn++) {
            int rr0 = row0 + warp_m + mt * 16 + r;
            int rr1 = rr0 + 8;
            int cc  = col0 + warp_n + nn * 8 + tq;
            if (MODE == 0) {
                if (rr0 < M) {
                    float2 v = make_float2(acc[mt][nn][0], acc[mt][nn][1]);
                    if (Dadd) { v.x += Dadd[(size_t)rr0 * N + cc]; v.y += Dadd[(size_t)rr0 * N + cc + 1]; }
                    *(float2*)&Cf[(size_t)rr0 * N + cc] = v;
                }
                if (rr1 < M) {
                    float2 v = make_float2(acc[mt][nn][2], acc[mt][nn][3]);
                    if (Dadd) { v.x += Dadd[(size_t)rr1 * N + cc]; v.y += Dadd[(size_t)rr1 * N + cc + 1]; }
                    *(float2*)&Cf[(size_t)rr1 * N + cc] = v;
                }
            } else if (MODE == 1) {
                int j = cc >> 1;   // cc even: (g,u) pair
                if (rr0 < M) {
                    float g = acc[mt][nn][0], u = acc[mt][nn][1];
                    float a = g / (1.0f + __expf(-g)) * u;
                    h16 hi, lo; split2h(a, hi, lo);
                    outh[(size_t)rr0 * 2 * halfW + j] = hi;
                    outh[(size_t)rr0 * 2 * halfW + halfW + j] = lo;
                }
                if (rr1 < M) {
                    float g = acc[mt][nn][2], u = acc[mt][nn][3];
                    float a = g / (1.0f + __expf(-g)) * u;
                    h16 hi, lo; split2h(a, hi, lo);
                    outh[(size_t)rr1 * 2 * halfW + j] = hi;
                    outh[(size_t)rr1 * 2 * halfW + halfW + j] = lo;
                }
            } else {  // MODE 2
                if (rr0 < M) {
                    int t = tok[rr0]; float w = wt[rr0];
                    atomicAdd(&OutAtom[(size_t)t * N + cc],     w * acc[mt][nn][0]);
                    atomicAdd(&OutAtom[(size_t)t * N + cc + 1], w * acc[mt][nn][1]);
                }
                if (rr1 < M) {
                    int t = tok[rr1]; float w = wt[rr1];
                    atomicAdd(&OutAtom[(size_t)t * N + cc],     w * acc[mt][nn][2]);
                    atomicAdd(&OutAtom[(size_t)t * N + cc + 1], w * acc[mt][nn][3]);
                }
            }
        }
    }
}

// ---------------- MoE routing ----------------
__global__ void gate_kernel(const float* __restrict__ m, const float* __restrict__ gw) {
    int t = blockIdx.x;
    __shared__ float logits[NE];
    int warp = threadIdx.x >> 5, lane = threadIdx.x & 31;
    const float* xr = m + (size_t)t * HH;
    const float* wr = gw + (size_t)warp * HH;
    float s = 0.0f;
    for (int i = lane; i < HH; i += 32) s += xr[i] * wr[i];
    for (int o = 16; o > 0; o >>= 1) s += __shfl_down_sync(0xffffffffu, s, o);
    if (lane == 0) logits[warp] = s;
    __syncthreads();
    if (threadIdx.x == 0) {
        float mx = logits[0];
        for (int e = 1; e < NE; e++) mx = fmaxf(mx, logits[e]);
        float p[NE]; float sum = 0.0f;
        for (int e = 0; e < NE; e++) { p[e] = __expf(logits[e] - mx); sum += p[e]; }
        for (int e = 0; e < NE; e++) p[e] /= sum;
        int i0 = 0;
        for (int e = 1; e < NE; e++) if (p[e] > p[i0]) i0 = e;
        int i1 = (i0 == 0) ? 1 : 0;
        for (int e = 0; e < NE; e++) if (e != i0 && p[e] > p[i1]) i1 = e;
        float inv = 1.0f / (p[i0] + p[i1]);
        int pos0 = atomicAdd(&g_cnt[i0], 1);
        g_tok[i0 * TT + pos0] = t; g_wt[i0 * TT + pos0] = p[i0] * inv;
        int pos1 = atomicAdd(&g_cnt[i1], 1);
        g_tok[i1 * TT + pos1] = t; g_wt[i1 * TT + pos1] = p[i1] * inv;
    }
}

__global__ void gather_split_kernel(const float* __restrict__ m) {
    int e = blockIdx.y, rr = blockIdx.x;
    if (rr >= g_cnt[e]) return;
    int t = g_tok[e * TT + rr];
    float4 v = ((const float4*)(m + (size_t)t * HH))[threadIdx.x];
    h16* oh = s_xe + ((size_t)e * TT + rr) * 2 * HH + threadIdx.x * 4;
    h16* ol = oh + HH;
    h16 hi, lo;
    split2h(v.x, hi, lo); oh[0] = hi; ol[0] = lo;
    split2h(v.y, hi, lo); oh[1] = hi; ol[1] = lo;
    split2h(v.z, hi, lo); oh[2] = hi; ol[2] = lo;
    split2h(v.w, hi, lo); oh[3] = hi; ol[3] = lo;
}

// ---------------- launch ----------------
static inline int grid4(long long elems) { return (int)((elems / 4 + 255) / 256); }

extern "C" void kernel_launch(void* const* d_in, const int* in_sizes, int n_in,
                              void* d_out, int out_size) {
    (void)in_sizes; (void)n_in; (void)out_size;
    const int*   positions = (const int*)  d_in[0];
    const float* hidden    = (const float*)d_in[1];
    const float* input_ln  = (const float*)d_in[2];
    const float* post_ln   = (const float*)d_in[3];
    const float* resid_ln  = (const float*)d_in[4];
    const float* qkv_w     = (const float*)d_in[5];
    const float* o_w       = (const float*)d_in[6];
    const float* gate_w    = (const float*)d_in[7];
    const float* ws        = (const float*)d_in[8];
    const float* w2s       = (const float*)d_in[9];
    const float* w13       = (const float*)d_in[10];
    const float* w2        = (const float*)d_in[11];
    float* out = (float*)d_out;

    float *p_qkv, *p_resattn, *p_m;
    h16 *p_sh, *p_sattn, *p_ssilu, *p_sqkvw, *p_sow, *p_sw13i, *p_sw2, *p_swsi, *p_sw2s, *p_sxe, *p_sact;
    cudaGetSymbolAddress((void**)&p_qkv,     g_qkv);
    cudaGetSymbolAddress((void**)&p_resattn, g_resattn);
    cudaGetSymbolAddress((void**)&p_m,       g_m);
    cudaGetSymbolAddress((void**)&p_sh,      s_h);
    cudaGetSymbolAddress((void**)&p_sattn,   s_attn);
    cudaGetSymbolAddress((void**)&p_ssilu,   s_silu);
    cudaGetSymbolAddress((void**)&p_sqkvw,   s_qkvw);
    cudaGetSymbolAddress((void**)&p_sow,     s_ow);
    cudaGetSymbolAddress((void**)&p_sw13i,   s_w13i);
    cudaGetSymbolAddress((void**)&p_sw2,     s_w2);
    cudaGetSymbolAddress((void**)&p_swsi,    s_wsi);
    cudaGetSymbolAddress((void**)&p_sw2s,    s_w2s);
    cudaGetSymbolAddress((void**)&p_sxe,     s_xe);
    cudaGetSymbolAddress((void**)&p_sact,    s_act);

    cudaFuncSetAttribute(attn_mma_kernel, cudaFuncAttributeMaxDynamicSharedMemorySize, ATT_SMEM);

    zero_cnt_kernel<<<1, 32>>>();

    // weight splits
    split_kernel<<<grid4((long long)QKVD * HH), 256>>>(qkv_w, p_sqkvw, HH, QKVD);
    split_kernel<<<grid4((long long)HH * HH), 256>>>(o_w, p_sow, HH, HH);
    split_interleave_kernel<<<grid4((long long)2 * HH * HH), 256>>>(w13, p_sw13i, HH, HH, 1);
    split_kernel<<<grid4((long long)HH * HH), 256>>>(w2, p_sw2, HH, HH);
    split_interleave_kernel<<<grid4((long long)NE * 2 * NI * HH), 256>>>(ws, p_swsi, HH, NI, NE);
    split_kernel<<<grid4((long long)NE * HH * NI), 256>>>(w2s, p_sw2s, NI, (long long)NE * HH);

    // h = rms_norm(hidden, input_ln_w)
    rmsnorm_split_kernel<<<TT, 256>>>(hidden, input_ln, p_sh);

    // qkv = h @ qkv_w.T
    gemm_kernel<0><<<dim3(QKVD / 128, TT / 128), 256>>>(
        p_sh, p_sqkvw, p_qkv, nullptr, nullptr, 0, nullptr, TT, QKVD, 2 * HH, 0, 0, 0);

    rope_kernel<<<(TT * (NHQ + NKVH) * 32 + 255) / 256, 256>>>(p_qkv, positions);

    attn_mma_kernel<<<dim3(TT / 64, NHQ), 256, ATT_SMEM>>>(p_qkv, p_sattn);

    // residual_attn = hidden + attn @ o_w.T
    gemm_kernel<0><<<dim3(HH / 128, TT / 128), 256>>>(
        p_sattn, p_sow, p_resattn, hidden, nullptr, 0, nullptr, TT, HH, 2 * HH, 0, 0, 0);

    // residual MLP (silu fused in epilogue; w2 GEMM writes d_out with residual add)
    rmsnorm_split_kernel<<<TT, 256>>>(p_resattn, resid_ln, p_sh);
    gemm_kernel<1><<<dim3(2 * HH / 128, TT / 128), 256>>>(
        p_sh, p_sw13i, nullptr, nullptr, p_ssilu, HH, nullptr, TT, 2 * HH, 2 * HH, 0, 0, 0);
    gemm_kernel<0><<<dim3(HH / 128, TT / 128), 256>>>(
        p_ssilu, p_sw2, out, p_resattn, nullptr, 0, nullptr, TT, HH, 2 * HH, 0, 0, 0);

    // MoE (scatter fused into down-proj epilogue, atomics onto out)
    rmsnorm_kernel<<<TT, 256>>>(p_resattn, post_ln, p_m);
    gate_kernel<<<TT, 256>>>(p_m, gate_w);
    gather_split_kernel<<<dim3(TT, NE), 256>>>(p_m);
    gemm_kernel<1><<<dim3(2 * NI / 128, TT / 128, NE), 256>>>(
        p_sxe, p_swsi, nullptr, nullptr, p_sact, NI, nullptr,
        TT, 2 * NI, 2 * HH,
        (long long)TT * 2 * HH, (long long)2 * NI * 2 * HH, (long long)TT * 2 * NI);
    gemm_kernel<2><<<dim3(HH / 128, TT / 128, NE), 256>>>(
        p_sact, p_sw2s, nullptr, nullptr, nullptr, 0, out,
        TT, HH, 2 * NI,
        (long long)TT * 2 * NI, (long long)HH * 2 * NI, 0);
}

// round 5
// speedup vs baseline: 15.8802x; 2.0151x over previous
#include <cuda_runtime.h>
#include <cuda_fp16.h>
#include <math.h>
#include <stdint.h>

#define TT   2048
#define HH   1024
#define NHQ  16
#define NKVH 4
#define HD   64
#define QKVD ((NHQ + 2*NKVH) * HD)   // 1536
#define NE   8
#define NI   2048
#define EPSV 1e-5f

typedef __half h16;

// ---------------- scratch (device globals; no allocations) ----------------
__device__ float g_qkv    [(size_t)TT * QKVD];
__device__ float g_resattn[(size_t)TT * HH];
__device__ float g_m      [(size_t)TT * HH];
__device__ int   g_cnt    [NE];
__device__ int   g_tok    [NE * TT];
__device__ float g_wt     [NE * TT];

// fp16 buffers (plain, no split)
__device__ __align__(16) h16 s_h    [(size_t)TT * HH];
__device__ __align__(16) h16 s_attn [(size_t)TT * HH];
__device__ __align__(16) h16 s_silu [(size_t)TT * HH];
__device__ __align__(16) h16 s_qkvw [(size_t)QKVD * HH];
__device__ __align__(16) h16 s_ow   [(size_t)HH * HH];
__device__ __align__(16) h16 s_w13i [(size_t)2 * HH * HH];      // interleaved g/u rows
__device__ __align__(16) h16 s_w2   [(size_t)HH * HH];
__device__ __align__(16) h16 s_wsi  [(size_t)NE * 2 * NI * HH]; // interleaved g/u rows
__device__ __align__(16) h16 s_w2s  [(size_t)NE * HH * NI];
__device__ __align__(16) h16 s_xe   [(size_t)NE * TT * HH];
__device__ __align__(16) h16 s_act  [(size_t)NE * TT * NI];

// ---------------- helpers ----------------
__device__ __forceinline__ void mma16816(float* c, const uint32_t* a, const uint32_t* b) {
    asm volatile(
        "mma.sync.aligned.m16n8k16.row.col.f32.f16.f16.f32 "
        "{%0,%1,%2,%3}, {%4,%5,%6,%7}, {%8,%9}, {%0,%1,%2,%3};"
        : "+f"(c[0]), "+f"(c[1]), "+f"(c[2]), "+f"(c[3])
        : "r"(a[0]), "r"(a[1]), "r"(a[2]), "r"(a[3]), "r"(b[0]), "r"(b[1]));
}

__device__ __forceinline__ void ldsm4(uint32_t* r, uint32_t addr) {
    asm volatile("ldmatrix.sync.aligned.m8n8.x4.shared.b16 {%0,%1,%2,%3}, [%4];"
        : "=r"(r[0]), "=r"(r[1]), "=r"(r[2]), "=r"(r[3]) : "r"(addr));
}

// ---------------- utility kernels ----------------
__global__ void zero_cnt_kernel() {
    if (threadIdx.x < NE) g_cnt[threadIdx.x] = 0;
}

// flat fp32 -> fp16 conversion
__global__ void conv_kernel(const float* __restrict__ in, h16* __restrict__ out,
                            long long total4) {
    long long idx = (long long)blockIdx.x * 256 + threadIdx.x;
    if (idx >= total4) return;
    float4 v = *(const float4*)&in[idx * 4];
    __half2 a = __floats2half2_rn(v.x, v.y);
    __half2 b = __floats2half2_rn(v.z, v.w);
    *(__half2*)&out[idx * 4]     = a;
    *(__half2*)&out[idx * 4 + 2] = b;
}

// fp32 -> fp16 with gate/up row interleave: out row 2j<-j, 2j+1<-I+j (per group)
__global__ void conv_interleave_kernel(const float* __restrict__ in, h16* __restrict__ out,
                                       int K, int I, int groups) {
    long long idx = (long long)blockIdx.x * 256 + threadIdx.x;
    int K4 = K >> 2;
    long long per_group = (long long)2 * I * K4;
    long long total4 = (long long)groups * per_group;
    if (idx >= total4) return;
    int g = (int)(idx / per_group);
    long long rem = idx % per_group;
    int r = (int)(rem / K4);
    int kq = (int)(rem % K4) * 4;
    int outr = (r < I) ? (2 * r) : (2 * (r - I) + 1);
    float4 v = *(const float4*)&in[((size_t)g * 2 * I + r) * K + kq];
    h16* o = out + ((size_t)g * 2 * I + outr) * K + kq;
    *(__half2*)&o[0] = __floats2half2_rn(v.x, v.y);
    *(__half2*)&o[2] = __floats2half2_rn(v.z, v.w);
}

__global__ void rmsnorm_kernel(const float* __restrict__ x,
                               const float* __restrict__ w,
                               float* __restrict__ o) {
    int t = blockIdx.x;
    float4 xv = ((const float4*)(x + (size_t)t * HH))[threadIdx.x];
    float s = xv.x * xv.x + xv.y * xv.y + xv.z * xv.z + xv.w * xv.w;
    __shared__ float red[256];
    red[threadIdx.x] = s;
    __syncthreads();
    for (int k = 128; k > 0; k >>= 1) {
        if (threadIdx.x < k) red[threadIdx.x] += red[threadIdx.x + k];
        __syncthreads();
    }
    float rs = rsqrtf(red[0] / (float)HH + EPSV);
    float4 wv = ((const float4*)w)[threadIdx.x];
    ((float4*)(o + (size_t)t * HH))[threadIdx.x] =
        make_float4(xv.x * rs * wv.x, xv.y * rs * wv.y, xv.z * rs * wv.z, xv.w * rs * wv.w);
}

__global__ void rmsnorm_h_kernel(const float* __restrict__ x,
                                 const float* __restrict__ w,
                                 h16* __restrict__ o) {
    int t = blockIdx.x;
    float4 xv = ((const float4*)(x + (size_t)t * HH))[threadIdx.x];
    float s = xv.x * xv.x + xv.y * xv.y + xv.z * xv.z + xv.w * xv.w;
    __shared__ float red[256];
    red[threadIdx.x] = s;
    __syncthreads();
    for (int k = 128; k > 0; k >>= 1) {
        if (threadIdx.x < k) red[threadIdx.x] += red[threadIdx.x + k];
        __syncthreads();
    }
    float rs = rsqrtf(red[0] / (float)HH + EPSV);
    float4 wv = ((const float4*)w)[threadIdx.x];
    h16* op = o + (size_t)t * HH + threadIdx.x * 4;
    *(__half2*)&op[0] = __floats2half2_rn(xv.x * rs * wv.x, xv.y * rs * wv.y);
    *(__half2*)&op[2] = __floats2half2_rn(xv.z * rs * wv.z, xv.w * rs * wv.w);
}

__global__ void rope_kernel(float* __restrict__ qkv, const int* __restrict__ positions) {
    int idx = blockIdx.x * 256 + threadIdx.x;
    if (idx >= TT * (NHQ + NKVH) * 32) return;
    int t = idx / ((NHQ + NKVH) * 32);
    int rem = idx % ((NHQ + NKVH) * 32);
    int h = rem >> 5;
    int d = rem & 31;
    int off = (h < NHQ) ? h * HD : NHQ * HD + (h - NHQ) * HD;
    float* p = qkv + (size_t)t * QKVD + off;
    float x1 = p[d];
    float x2 = p[d + 32];
    float pos = (float)positions[t];
    float invf = __expf(-0.2878231366f * (float)d);   // ln(10000)/32
    float fr = pos * invf;
    float c, s;
    __sincosf(fr, &s, &c);
    p[d]      = x1 * c - x2 * s;
    p[d + 32] = x2 * c + x1 * s;
}

// ---------------- tensor-core flash attention: 64x64 tiles, fp16 ----------------
// smem: Qh[64][72], Kh[64][72], Vh[64][72] (V^T: [d][j]), Ph[64][72], Ss[64][66] f32, stats 3x64
#define ATT_SMEM (4 * 64 * 72 * 2 + 64 * 66 * 4 + 3 * 64 * 4)

__global__ __launch_bounds__(256) void attn_mma_kernel(
    const float* __restrict__ qkv, h16* __restrict__ outH) {
    extern __shared__ char smraw[];
    h16*  Qh = (h16*)smraw;
    h16*  Kh = Qh + 64 * 72;
    h16*  Vh = Kh + 64 * 72;
    h16*  Ph = Vh + 64 * 72;
    float* Ss  = (float*)(Ph + 64 * 72);
    float* sm_s = Ss + 64 * 66;
    float* sl_s = sm_s + 64;
    float* sc_s = sl_s + 64;

    int qt = blockIdx.x, h = blockIdx.y;
    int kvh = h >> 2;
    int tid = threadIdx.x, lane = tid & 31, wid = tid >> 5;
    int warp_m = (wid >> 1) * 16, warp_n = (wid & 1) * 32;
    int r = lane >> 2, tq = (lane & 3) * 2;

    // load + convert Q tile
    for (int i = tid; i < 64 * 16; i += 256) {
        int row = i >> 4, c = (i & 15) << 2;
        float4 v = *(const float4*)&qkv[(size_t)(qt * 64 + row) * QKVD + h * HD + c];
        h16* qp = Qh + row * 72 + c;
        *(__half2*)&qp[0] = __floats2half2_rn(v.x, v.y);
        *(__half2*)&qp[2] = __floats2half2_rn(v.z, v.w);
    }
    if (tid < 64) { sm_s[tid] = -1e30f; sl_s[tid] = 0.0f; }

    float oacc[4][4] = {};
    for (int kt = 0; kt <= qt; kt++) {
        __syncthreads();
        for (int i = tid; i < 64 * 16; i += 256) {
            int row = i >> 4, c = (i & 15) << 2;
            size_t base = (size_t)(kt * 64 + row) * QKVD + NHQ * HD + kvh * HD;
            float4 kv = *(const float4*)&qkv[base + c];
            h16* kp = Kh + row * 72 + c;
            *(__half2*)&kp[0] = __floats2half2_rn(kv.x, kv.y);
            *(__half2*)&kp[2] = __floats2half2_rn(kv.z, kv.w);
            float4 vv = *(const float4*)&qkv[base + NKVH * HD + c];
            Vh[(c + 0) * 72 + row] = __float2half(vv.x);
            Vh[(c + 1) * 72 + row] = __float2half(vv.y);
            Vh[(c + 2) * 72 + row] = __float2half(vv.z);
            Vh[(c + 3) * 72 + row] = __float2half(vv.w);
        }
        __syncthreads();

        // S = Q @ K^T  (K = 64)
        float sacc[4][4] = {};
        #pragma unroll
        for (int kb = 0; kb < 4; kb++) {
            int kbo = kb * 16;
            uint32_t af[4];
            af[0] = *(const uint32_t*)&Qh[(warp_m + r) * 72 + kbo + tq];
            af[1] = *(const uint32_t*)&Qh[(warp_m + r + 8) * 72 + kbo + tq];
            af[2] = *(const uint32_t*)&Qh[(warp_m + r) * 72 + kbo + tq + 8];
            af[3] = *(const uint32_t*)&Qh[(warp_m + r + 8) * 72 + kbo + tq + 8];
            #pragma unroll
            for (int nn = 0; nn < 4; nn++) {
                uint32_t bf[2];
                bf[0] = *(const uint32_t*)&Kh[(warp_n + nn * 8 + r) * 72 + kbo + tq];
                bf[1] = *(const uint32_t*)&Kh[(warp_n + nn * 8 + r) * 72 + kbo + tq + 8];
                mma16816(sacc[nn], af, bf);
            }
        }
        #pragma unroll
        for (int nn = 0; nn < 4; nn++) {
            int col = warp_n + nn * 8 + tq;
            *(float2*)&Ss[(warp_m + r) * 66 + col]     = make_float2(sacc[nn][0], sacc[nn][1]);
            *(float2*)&Ss[(warp_m + r + 8) * 66 + col] = make_float2(sacc[nn][2], sacc[nn][3]);
        }
        __syncthreads();

        // online softmax: 4 threads per row
        {
            int row = tid >> 2, sub = tid & 3;
            float rm = -1e30f;
            #pragma unroll
            for (int jj = 0; jj < 16; jj++) {
                int j = sub * 16 + jj;
                float s = Ss[row * 66 + j] * 0.125f;
                if (kt == qt && j > row) s = -1e30f;
                Ss[row * 66 + j] = s;
                rm = fmaxf(rm, s);
            }
            rm = fmaxf(rm, __shfl_xor_sync(0xffffffffu, rm, 1));
            rm = fmaxf(rm, __shfl_xor_sync(0xffffffffu, rm, 2));
            float oldm = sm_s[row];
            float newm = fmaxf(oldm, rm);
            float sum = 0.0f;
            #pragma unroll
            for (int jj = 0; jj < 16; jj += 2) {
                int j = sub * 16 + jj;
                float p0 = __expf(Ss[row * 66 + j] - newm);
                float p1 = __expf(Ss[row * 66 + j + 1] - newm);
                sum += p0 + p1;
                *(__half2*)&Ph[row * 72 + j] = __floats2half2_rn(p0, p1);
            }
            sum += __shfl_xor_sync(0xffffffffu, sum, 1);
            sum += __shfl_xor_sync(0xffffffffu, sum, 2);
            if (sub == 0) {
                float corr = __expf(oldm - newm);
                sl_s[row] = sl_s[row] * corr + sum;
                sc_s[row] = corr;
                sm_s[row] = newm;
            }
        }
        __syncthreads();

        // O = O*corr + P @ V
        float c0 = sc_s[warp_m + r], c1 = sc_s[warp_m + r + 8];
        #pragma unroll
        for (int nn = 0; nn < 4; nn++) {
            oacc[nn][0] *= c0; oacc[nn][1] *= c0;
            oacc[nn][2] *= c1; oacc[nn][3] *= c1;
        }
        #pragma unroll
        for (int kb = 0; kb < 4; kb++) {
            int kbo = kb * 16;
            uint32_t af[4];
            af[0] = *(const uint32_t*)&Ph[(warp_m + r) * 72 + kbo + tq];
            af[1] = *(const uint32_t*)&Ph[(warp_m + r + 8) * 72 + kbo + tq];
            af[2] = *(const uint32_t*)&Ph[(warp_m + r) * 72 + kbo + tq + 8];
            af[3] = *(const uint32_t*)&Ph[(warp_m + r + 8) * 72 + kbo + tq + 8];
            #pragma unroll
            for (int nn = 0; nn < 4; nn++) {
                uint32_t bf[2];
                bf[0] = *(const uint32_t*)&Vh[(warp_n + nn * 8 + r) * 72 + kbo + tq];
                bf[1] = *(const uint32_t*)&Vh[(warp_n + nn * 8 + r) * 72 + kbo + tq + 8];
                mma16816(oacc[nn], af, bf);
            }
        }
    }

    float inv0 = 1.0f / sl_s[warp_m + r];
    float inv1 = 1.0f / sl_s[warp_m + r + 8];
    int q0 = qt * 64 + warp_m + r;
    int q1 = q0 + 8;
    #pragma unroll
    for (int nn = 0; nn < 4; nn++) {
        int d0 = h * HD + warp_n + nn * 8 + tq;
        *(__half2*)&outH[(size_t)q0 * HH + d0] =
            __floats2half2_rn(oacc[nn][0] * inv0, oacc[nn][1] * inv0);
        *(__half2*)&outH[(size_t)q1 * HH + d0] =
            __floats2half2_rn(oacc[nn][2] * inv1, oacc[nn][3] * inv1);
    }
}

// ---------------- fp16 tensor-core GEMM with ldmatrix, templated epilogue ----------------
// MODE 0: Cf = A*B^T (+ Dadd if non-null)
// MODE 1: (even,odd) col pairs = (g,u) -> silu(g)*u into OutH (width halfW)
// MODE 2: atomicAdd(OutAtom[tok[row]*N + col] += wt[row]*val)
#define GBUF (128 * 40 * 2)   // bytes per smem buffer

template<int MODE>
__global__ __launch_bounds__(256) void gemm_kernel(
    const h16* __restrict__ Aall, const h16* __restrict__ Ball,
    float* __restrict__ Cf, const float* __restrict__ Dadd,
    h16* __restrict__ OutH, int halfW,
    float* __restrict__ OutAtom,
    int M0, int N, int K,
    long long Asl, long long Bsl, long long OslH) {

    int e = (gridDim.z > 1) ? blockIdx.z : 0;
    int M = (gridDim.z > 1) ? g_cnt[e] : M0;
    if ((int)blockIdx.y * 128 >= M) return;
    const h16* A = Aall + (size_t)e * Asl;
    const h16* B = Ball + (size_t)e * Bsl;

    __shared__ __align__(16) h16 As[2][128][40];
    __shared__ __align__(16) h16 Bs[2][128][40];
    const int tid = threadIdx.x;
    const int lane = tid & 31;
    const int wid = tid >> 5;
    const int warp_m = (wid >> 2) * 64;
    const int warp_n = (wid & 3) * 32;
    const int row0 = blockIdx.y * 128;
    const int col0 = blockIdx.x * 128;

    const int lr = tid >> 1;
    const int lc = (tid & 1) * 8;
    int arow = row0 + lr; if (arow >= M) arow = M - 1;
    const h16* aptr = A + (size_t)arow * K + lc;
    const h16* bptr = B + (size_t)(col0 + lr) * K + lc;

    uint32_t asm_base = (uint32_t)__cvta_generic_to_shared(&As[0][0][0]);
    uint32_t bsm_base = (uint32_t)__cvta_generic_to_shared(&Bs[0][0][0]);
    // ldmatrix per-lane offsets (bytes)
    uint32_t aoff = asm_base + (uint32_t)((warp_m + (lane & 15)) * 80 + ((lane >> 4) << 4));
    uint32_t boff = bsm_base + (uint32_t)((warp_n + (lane & 7) + ((lane >> 4) << 3)) * 80
                                          + (((lane >> 3) & 1) << 4));

    float acc[4][4][4] = {};

    float4 av0 = *(const float4*)aptr;
    float4 av1 = *(const float4*)(aptr + 16);
    float4 bv0 = *(const float4*)bptr;
    float4 bv1 = *(const float4*)(bptr + 16);
    *(float4*)&As[0][lr][lc] = av0; *(float4*)&As[0][lr][lc + 16] = av1;
    *(float4*)&Bs[0][lr][lc] = bv0; *(float4*)&Bs[0][lr][lc + 16] = bv1;
    __syncthreads();

    const int nt = K >> 5;
    const int r  = lane >> 2;
    const int tq = (lane & 3) * 2;
    for (int kt = 0; kt < nt; kt++) {
        int cur = kt & 1;
        uint32_t abase = aoff + cur * GBUF;
        uint32_t bbase = boff + cur * GBUF;
        if (kt + 1 < nt) {
            const h16* ap = aptr + (kt + 1) * 32;
            const h16* bp = bptr + (kt + 1) * 32;
            av0 = *(const float4*)ap; av1 = *(const float4*)(ap + 16);
            bv0 = *(const float4*)bp; bv1 = *(const float4*)(bp + 16);
        }
        #pragma unroll
        for (int ks = 0; ks < 2; ks++) {
            const uint32_t kbb = ks * 32;   // 16 halfs = 32 bytes
            uint32_t afr[4][4], bfr2[2][4];
            #pragma unroll
            for (int mt = 0; mt < 4; mt++)
                ldsm4(afr[mt], abase + mt * (16 * 80) + kbb);
            #pragma unroll
            for (int pr = 0; pr < 2; pr++)
                ldsm4(bfr2[pr], bbase + pr * (16 * 80) + kbb);
            #pragma unroll
            for (int mt = 0; mt < 4; mt++) {
                #pragma unroll
                for (int nn = 0; nn < 4; nn++) {
                    uint32_t bf[2] = { bfr2[nn >> 1][(nn & 1) * 2],
                                       bfr2[nn >> 1][(nn & 1) * 2 + 1] };
                    mma16816(acc[mt][nn], afr[mt], bf);
                }
            }
        }
        if (kt + 1 < nt) {
            int nb = cur ^ 1;
            *(float4*)&As[nb][lr][lc] = av0; *(float4*)&As[nb][lr][lc + 16] = av1;
            *(float4*)&Bs[nb][lr][lc] = bv0; *(float4*)&Bs[nb][lr][lc + 16] = bv1;
        }
        __syncthreads();
    }

    const int* tok = g_tok + e * TT;
    const float* wt = g_wt + e * TT;
    h16* outh = (MODE == 1) ? (OutH + (size_t)e * OslH) : OutH;

    #pragma unroll
    for (int mt = 0; mt < 4; mt++) {
        #pragma unroll
        for (int nn = 0; nn < 4; nn++) {
            int rr0 = row0 + warp_m + mt * 16 + r;
            int rr1 = rr0 + 8;
            int cc  = col0 + warp_n + nn * 8 + tq;
            if (MODE == 0) {
                if (rr0 < M) {
                    float2 v = make_float2(acc[mt][nn][0], acc[mt][nn][1]);
                    if (Dadd) { v.x += Dadd[(size_t)rr0 * N + cc]; v.y += Dadd[(size_t)rr0 * N + cc + 1]; }
                    *(float2*)&Cf[(size_t)rr0 * N + cc] = v;
                }
                if (rr1 < M) {
                    float2 v = make_float2(acc[mt][nn][2], acc[mt][nn][3]);
                    if (Dadd) { v.x += Dadd[(size_t)rr1 * N + cc]; v.y += Dadd[(size_t)rr1 * N + cc + 1]; }
                    *(float2*)&Cf[(size_t)rr1 * N + cc] = v;
                }
            } else if (MODE == 1) {
                int j = cc >> 1;
                if (rr0 < M) {
                    float g = acc[mt][nn][0], u = acc[mt][nn][1];
                    outh[(size_t)rr0 * halfW + j] = __float2half(g / (1.0f + __expf(-g)) * u);
                }
                if (rr1 < M) {
                    float g = acc[mt][nn][2], u = acc[mt][nn][3];
                    outh[(size_t)rr1 * halfW + j] = __float2half(g / (1.0f + __expf(-g)) * u);
                }
            } else {  // MODE 2
                if (rr0 < M) {
                    int t = tok[rr0]; float w = wt[rr0];
                    atomicAdd(&OutAtom[(size_t)t * N + cc],     w * acc[mt][nn][0]);
                    atomicAdd(&OutAtom[(size_t)t * N + cc + 1], w * acc[mt][nn][1]);
                }
                if (rr1 < M) {
                    int t = tok[rr1]; float w = wt[rr1];
                    atomicAdd(&OutAtom[(size_t)t * N + cc],     w * acc[mt][nn][2]);
                    atomicAdd(&OutAtom[(size_t)t * N + cc + 1], w * acc[mt][nn][3]);
                }
            }
        }
    }
}

// ---------------- MoE routing ----------------
__global__ void gate_kernel(const float* __restrict__ m, const float* __restrict__ gw) {
    int t = blockIdx.x;
    __shared__ float logits[NE];
    int warp = threadIdx.x >> 5, lane = threadIdx.x & 31;
    const float* xr = m + (size_t)t * HH;
    const float* wr = gw + (size_t)warp * HH;
    float s = 0.0f;
    for (int i = lane; i < HH; i += 32) s += xr[i] * wr[i];
    for (int o = 16; o > 0; o >>= 1) s += __shfl_down_sync(0xffffffffu, s, o);
    if (lane == 0) logits[warp] = s;
    __syncthreads();
    if (threadIdx.x == 0) {
        float mx = logits[0];
        for (int e = 1; e < NE; e++) mx = fmaxf(mx, logits[e]);
        float p[NE]; float sum = 0.0f;
        for (int e = 0; e < NE; e++) { p[e] = __expf(logits[e] - mx); sum += p[e]; }
        for (int e = 0; e < NE; e++) p[e] /= sum;
        int i0 = 0;
        for (int e = 1; e < NE; e++) if (p[e] > p[i0]) i0 = e;
        int i1 = (i0 == 0) ? 1 : 0;
        for (int e = 0; e < NE; e++) if (e != i0 && p[e] > p[i1]) i1 = e;
        float inv = 1.0f / (p[i0] + p[i1]);
        int pos0 = atomicAdd(&g_cnt[i0], 1);
        g_tok[i0 * TT + pos0] = t; g_wt[i0 * TT + pos0] = p[i0] * inv;
        int pos1 = atomicAdd(&g_cnt[i1], 1);
        g_tok[i1 * TT + pos1] = t; g_wt[i1 * TT + pos1] = p[i1] * inv;
    }
}

__global__ void gather_h_kernel(const float* __restrict__ m) {
    int e = blockIdx.y, rr = blockIdx.x;
    if (rr >= g_cnt[e]) return;
    int t = g_tok[e * TT + rr];
    float4 v = ((const float4*)(m + (size_t)t * HH))[threadIdx.x];
    h16* o = s_xe + ((size_t)e * TT + rr) * HH + threadIdx.x * 4;
    *(__half2*)&o[0] = __floats2half2_rn(v.x, v.y);
    *(__half2*)&o[2] = __floats2half2_rn(v.z, v.w);
}

// ---------------- launch ----------------
static inline int grid4(long long elems) { return (int)((elems / 4 + 255) / 256); }

extern "C" void kernel_launch(void* const* d_in, const int* in_sizes, int n_in,
                              void* d_out, int out_size) {
    (void)in_sizes; (void)n_in; (void)out_size;
    const int*   positions = (const int*)  d_in[0];
    const float* hidden    = (const float*)d_in[1];
    const float* input_ln  = (const float*)d_in[2];
    const float* post_ln   = (const float*)d_in[3];
    const float* resid_ln  = (const float*)d_in[4];
    const float* qkv_w     = (const float*)d_in[5];
    const float* o_w       = (const float*)d_in[6];
    const float* gate_w    = (const float*)d_in[7];
    const float* ws        = (const float*)d_in[8];
    const float* w2s       = (const float*)d_in[9];
    const float* w13       = (const float*)d_in[10];
    const float* w2        = (const float*)d_in[11];
    float* out = (float*)d_out;

    float *p_qkv, *p_resattn, *p_m;
    h16 *p_sh, *p_sattn, *p_ssilu, *p_sqkvw, *p_sow, *p_sw13i, *p_sw2, *p_swsi, *p_sw2s, *p_sxe, *p_sact;
    cudaGetSymbolAddress((void**)&p_qkv,     g_qkv);
    cudaGetSymbolAddress((void**)&p_resattn, g_resattn);
    cudaGetSymbolAddress((void**)&p_m,       g_m);
    cudaGetSymbolAddress((void**)&p_sh,      s_h);
    cudaGetSymbolAddress((void**)&p_sattn,   s_attn);
    cudaGetSymbolAddress((void**)&p_ssilu,   s_silu);
    cudaGetSymbolAddress((void**)&p_sqkvw,   s_qkvw);
    cudaGetSymbolAddress((void**)&p_sow,     s_ow);
    cudaGetSymbolAddress((void**)&p_sw13i,   s_w13i);
    cudaGetSymbolAddress((void**)&p_sw2,     s_w2);
    cudaGetSymbolAddress((void**)&p_swsi,    s_wsi);
    cudaGetSymbolAddress((void**)&p_sw2s,    s_w2s);
    cudaGetSymbolAddress((void**)&p_sxe,     s_xe);
    cudaGetSymbolAddress((void**)&p_sact,    s_act);

    cudaFuncSetAttribute(attn_mma_kernel, cudaFuncAttributeMaxDynamicSharedMemorySize, ATT_SMEM);

    zero_cnt_kernel<<<1, 32>>>();

    // weight conversions (flat except gate/up interleaves)
    conv_kernel<<<grid4((long long)QKVD * HH), 256>>>(qkv_w, p_sqkvw, (long long)QKVD * HH / 4);
    conv_kernel<<<grid4((long long)HH * HH), 256>>>(o_w, p_sow, (long long)HH * HH / 4);
    conv_interleave_kernel<<<grid4((long long)2 * HH * HH), 256>>>(w13, p_sw13i, HH, HH, 1);
    conv_kernel<<<grid4((long long)HH * HH), 256>>>(w2, p_sw2, (long long)HH * HH / 4);
    conv_interleave_kernel<<<grid4((long long)NE * 2 * NI * HH), 256>>>(ws, p_swsi, HH, NI, NE);
    conv_kernel<<<grid4((long long)NE * HH * NI), 256>>>(w2s, p_sw2s, (long long)NE * HH * NI / 4);

    // h = rms_norm(hidden, input_ln_w)
    rmsnorm_h_kernel<<<TT, 256>>>(hidden, input_ln, p_sh);

    // qkv = h @ qkv_w.T
    gemm_kernel<0><<<dim3(QKVD / 128, TT / 128), 256>>>(
        p_sh, p_sqkvw, p_qkv, nullptr, nullptr, 0, nullptr, TT, QKVD, HH, 0, 0, 0);

    rope_kernel<<<(TT * (NHQ + NKVH) * 32 + 255) / 256, 256>>>(p_qkv, positions);

    attn_mma_kernel<<<dim3(TT / 64, NHQ), 256, ATT_SMEM>>>(p_qkv, p_sattn);

    // residual_attn = hidden + attn @ o_w.T
    gemm_kernel<0><<<dim3(HH / 128, TT / 128), 256>>>(
        p_sattn, p_sow, p_resattn, hidden, nullptr, 0, nullptr, TT, HH, HH, 0, 0, 0);

    // residual MLP
    rmsnorm_h_kernel<<<TT, 256>>>(p_resattn, resid_ln, p_sh);
    gemm_kernel<1><<<dim3(2 * HH / 128, TT / 128), 256>>>(
        p_sh, p_sw13i, nullptr, nullptr, p_ssilu, HH, nullptr, TT, 2 * HH, HH, 0, 0, 0);
    gemm_kernel<0><<<dim3(HH / 128, TT / 128), 256>>>(
        p_ssilu, p_sw2, out, p_resattn, nullptr, 0, nullptr, TT, HH, HH, 0, 0, 0);

    // MoE
    rmsnorm_kernel<<<TT, 256>>>(p_resattn, post_ln, p_m);
    gate_kernel<<<TT, 256>>>(p_m, gate_w);
    gather_h_kernel<<<dim3(TT, NE), 256>>>(p_m);
    gemm_kernel<1><<<dim3(2 * NI / 128, TT / 128, NE), 256>>>(
        p_sxe, p_swsi, nullptr, nullptr, p_sact, NI, nullptr,
        TT, 2 * NI, HH,
        (long long)TT * HH, (long long)2 * NI * HH, (long long)TT * NI);
    gemm_kernel<2><<<dim3(HH / 128, TT / 128, NE), 256>>>(
        p_sact, p_sw2s, nullptr, nullptr, nullptr, 0, out,
        TT, HH, NI,
        (long long)TT * NI, (long long)HH * NI, 0);
}